// round 4
// baseline (speedup 1.0000x reference)
#include <cuda_runtime.h>
#include <math.h>

#define NRAYS 8192
#define NS    128
#define NT    256        // threads per block (2 per sample)
#define NC    32
#define NH    64
#define NG    128
#define RPB   8          // rays per block

// dynamic smem layout (float offsets)
#define OFF_WT1   0        // 2048
#define OFF_WT2   2048     // 4096
#define OFF_WO1   6144     // 4096
#define OFF_WC1   10240    // 4096
#define OFF_WR    14336    // 1344
#define OFF_WO2   15680    // 64
#define OFF_WC2   15744    // 192
#define OFF_BT1   15936    // 64
#define OFF_BT2   16000    // 64
#define OFF_BO1   16064    // 64
#define OFF_BC1   16128    // 64
#define OFF_BR    16192    // 64
#define OFF_RAY   16256    // 64
#define OFF_HE    16320    // 21 (pad 24)
#define OFF_WTOT  16344    // 4
#define OFF_PART  16348    // 12
#define OFF_MISC  16360    // bo2(1)+bc2(3)
#define OFF_AM    16364    // 128
#define OFF_C0    16492    // 128
#define OFF_C1    16620    // 128
#define OFF_C2    16748    // 128
#define SMEM_FLOATS 16876
#define SMEM_BYTES (SMEM_FLOATS * 4)

__device__ __forceinline__ float frelu(float x) { return x > 0.f ? x : 0.f; }

__device__ __forceinline__ unsigned long long pack2(float a) {
    unsigned long long r;
    unsigned u = __float_as_uint(a);
    asm("mov.b64 %0, {%1, %1};" : "=l"(r) : "r"(u));
    return r;
}
__device__ __forceinline__ void fma2(unsigned long long& d,
                                     unsigned long long a,
                                     unsigned long long b) {
    asm("fma.rn.f32x2 %0, %1, %2, %0;" : "+l"(d) : "l"(a), "l"(b));
}
__device__ __forceinline__ void unpack2(unsigned long long v, float& lo, float& hi) {
    unsigned l, h;
    asm("mov.b64 {%0, %1}, %2;" : "=r"(l), "=r"(h) : "l"(v));
    lo = __uint_as_float(l);
    hi = __uint_as_float(h);
}

// acc[16] (u64, 32 packed outputs) init from bias slice.
__device__ __forceinline__ void acc_init(unsigned long long* acc,
                                         const float* sb_half) {
    const ulonglong2* b2 = (const ulonglong2*)sb_half;
#pragma unroll
    for (int o = 0; o < 8; o++) {
        ulonglong2 b = b2[o];
        acc[2 * o] = b.x;
        acc[2 * o + 1] = b.y;
    }
}
// accumulate one input feature into 32 packed outputs.
__device__ __forceinline__ void acc_row(unsigned long long* acc, float f,
                                        const float* wrow) {
    unsigned long long f2 = pack2(f);
    const ulonglong2* w2 = (const ulonglong2*)wrow;
#pragma unroll
    for (int o = 0; o < 8; o++) {
        ulonglong2 w = w2[o];
        fma2(acc[2 * o], f2, w.x);
        fma2(acc[2 * o + 1], f2, w.y);
    }
}
__device__ __forceinline__ void acc_out(const unsigned long long* acc, float* v) {
#pragma unroll
    for (int o = 0; o < 16; o++) unpack2(acc[o], v[2 * o], v[2 * o + 1]);
}

// split dense 64->64: own[32] holds inputs (half*32..), partner holds the rest.
// Computes this thread's 32 outputs (cols half*32..) into outv.
__device__ __forceinline__ void dense_split(const float* own, const float* sW,
                                            const float* sb, int half,
                                            float* outv) {
    unsigned long long acc[16];
    const int cbase = half * 32;
    acc_init(acc, sb + cbase);
#pragma unroll
    for (int k = 0; k < 32; k++) {
        float f0 = own[k];
        float f1 = __shfl_xor_sync(0xffffffffu, f0, 1);
        int a = cbase + k;       // own input's global row
        int b = a ^ 32;          // partner input's global row
        acc_row(acc, f0, sW + a * NH + cbase);
        acc_row(acc, f1, sW + b * NH + cbase);
    }
    acc_out(acc, outv);
}

__global__ void __launch_bounds__(NT, 2)
lightplane_kernel(const float* __restrict__ origins,
                  const float* __restrict__ directions,
                  const float* __restrict__ nearv,
                  const float* __restrict__ farv,
                  const float* __restrict__ grid,
                  const float* __restrict__ Wr,  const float* __restrict__ br,
                  const float* __restrict__ Wt1, const float* __restrict__ bt1,
                  const float* __restrict__ Wt2, const float* __restrict__ bt2,
                  const float* __restrict__ Wo1, const float* __restrict__ bo1,
                  const float* __restrict__ Wo2, const float* __restrict__ bo2,
                  const float* __restrict__ Wc1, const float* __restrict__ bc1,
                  const float* __restrict__ Wc2, const float* __restrict__ bc2,
                  float* __restrict__ out) {
    extern __shared__ float sm[];
    const int tid = threadIdx.x;
    const int half = tid & 1;
    const int s = tid >> 1;          // sample index 0..127
    const int cbase = half * 32;

    // ---- stage all weights (once per block) ----
    {
        const float4* g;
        float4* sp;
        g = (const float4*)Wt1; sp = (float4*)(sm + OFF_WT1);
        for (int i = tid; i < 512; i += NT) sp[i] = g[i];
        g = (const float4*)Wt2; sp = (float4*)(sm + OFF_WT2);
        for (int i = tid; i < 1024; i += NT) sp[i] = g[i];
        g = (const float4*)Wo1; sp = (float4*)(sm + OFF_WO1);
        for (int i = tid; i < 1024; i += NT) sp[i] = g[i];
        g = (const float4*)Wc1; sp = (float4*)(sm + OFF_WC1);
        for (int i = tid; i < 1024; i += NT) sp[i] = g[i];
        g = (const float4*)Wr; sp = (float4*)(sm + OFF_WR);
        for (int i = tid; i < 336; i += NT) sp[i] = g[i];
        if (tid < 16)               ((float4*)(sm + OFF_WO2))[tid]       = ((const float4*)Wo2)[tid];
        if (tid >= 128 && tid < 176)((float4*)(sm + OFF_WC2))[tid - 128] = ((const float4*)Wc2)[tid - 128];
        if (tid >= 16 && tid < 32)  ((float4*)(sm + OFF_BT1))[tid - 16]  = ((const float4*)bt1)[tid - 16];
        if (tid >= 32 && tid < 48)  ((float4*)(sm + OFF_BT2))[tid - 32]  = ((const float4*)bt2)[tid - 32];
        if (tid >= 48 && tid < 64)  ((float4*)(sm + OFF_BO1))[tid - 48]  = ((const float4*)bo1)[tid - 48];
        if (tid >= 64 && tid < 80)  ((float4*)(sm + OFF_BC1))[tid - 64]  = ((const float4*)bc1)[tid - 64];
        if (tid >= 80 && tid < 96)  ((float4*)(sm + OFF_BR))[tid - 80]   = ((const float4*)br)[tid - 80];
        if (tid == 96) sm[OFF_MISC] = bo2[0];
        if (tid >= 97 && tid < 100) sm[OFF_MISC + 1 + tid - 97] = bc2[tid - 97];
    }
    __syncthreads();

    for (int rr = 0; rr < RPB; rr++) {
        const int ray = blockIdx.x * RPB + rr;
        const float dx = directions[ray * 3 + 0];
        const float dy = directions[ray * 3 + 1];
        const float dz = directions[ray * 3 + 2];
        const float nr = nearv[ray];
        const float fa = farv[ray];
        const float ox = origins[ray * 3 + 0];
        const float oy = origins[ray * 3 + 1];
        const float oz = origins[ray * 3 + 2];

        // harmonic encoding (per ray)
        if (tid < 9) {
            int f = tid / 3, d = tid % 3;
            float dv = (d == 0) ? dx : ((d == 1) ? dy : dz);
            float ang = dv * (float)(1 << f);
            sm[OFF_HE + tid]     = sinf(ang);
            sm[OFF_HE + 9 + tid] = cosf(ang);
        }
        if (tid >= 9 && tid < 12) {
            int d = tid - 9;
            sm[OFF_HE + 18 + d] = (d == 0) ? dx : ((d == 1) ? dy : dz);
        }
        __syncthreads();                          // HE ready
        if (tid < NH) {
            float a = sm[OFF_BR + tid];
#pragma unroll
            for (int k = 0; k < 21; k++)
                a = fmaf(sm[OFF_HE + k], sm[OFF_WR + k * NH + tid], a);
            sm[OFF_RAY + tid] = a;
        }

        // ---- per-sample: thread pair (s, half) ----
        const float t = nr + (fa - nr) * (((float)s + 0.5f) / (float)NS);
        const float px = ox + t * dx;
        const float py = oy + t * dy;
        const float pz = oz + t * dz;

        // trilinear gather (both threads of a pair compute identical feats)
        float feats[NC];
        {
            unsigned long long fac[16];
#pragma unroll
            for (int q = 0; q < 16; q++) fac[q] = 0ull;
            const float scale = 0.5f * (float)(NG - 1);
            float cx = (px + 1.f) * scale;
            float cy = (py + 1.f) * scale;
            float cz = (pz + 1.f) * scale;
            float fx = cx - floorf(cx), fy = cy - floorf(cy), fz = cz - floorf(cz);
            int x0 = min(max((int)floorf(cx), 0), NG - 1);
            int y0 = min(max((int)floorf(cy), 0), NG - 1);
            int z0 = min(max((int)floorf(cz), 0), NG - 1);
            int x1 = min(x0 + 1, NG - 1);
            int y1 = min(y0 + 1, NG - 1);
            int z1 = min(z0 + 1, NG - 1);
            float wx[2] = {1.f - fx, fx};
            float wy[2] = {1.f - fy, fy};
            float wz[2] = {1.f - fz, fz};
            int xs[2] = {x0, x1}, ys[2] = {y0, y1}, zs[2] = {z0, z1};
#pragma unroll
            for (int a = 0; a < 2; a++)
#pragma unroll
                for (int b = 0; b < 2; b++)
#pragma unroll
                    for (int c = 0; c < 2; c++) {
                        unsigned long long wp = pack2(wx[a] * wy[b] * wz[c]);
                        const ulonglong2* g2 = (const ulonglong2*)(grid +
                            ((size_t)((zs[c] * NG + ys[b]) * NG + xs[a])) * NC);
#pragma unroll
                        for (int q = 0; q < 8; q++) {
                            ulonglong2 v = g2[q];
                            fma2(fac[2 * q], wp, v.x);
                            fma2(fac[2 * q + 1], wp, v.y);
                        }
                    }
#pragma unroll
            for (int q = 0; q < 16; q++) unpack2(fac[q], feats[2 * q], feats[2 * q + 1]);
        }

        // layer 1: 32 -> own 32 (full input in regs)
        float e1[32];
        {
            unsigned long long acc[16];
            acc_init(acc, sm + OFF_BT1 + cbase);
#pragma unroll
            for (int i = 0; i < NC; i++)
                acc_row(acc, feats[i], sm + OFF_WT1 + i * NH + cbase);
            acc_out(acc, e1);
        }
#pragma unroll
        for (int o = 0; o < 32; o++) e1[o] = frelu(e1[o]);

        // layer 2: 64 -> own 32
        float e[32];
        dense_split(e1, sm + OFF_WT2, sm + OFF_BT2, half, e);
#pragma unroll
        for (int o = 0; o < 32; o++) e[o] = frelu(e[o]);

        // opacity head: h = relu(e@Wo1+bo1); raw = h . Wo2 + bo2
        float h[32];
        dense_split(e, sm + OFF_WO1, sm + OFF_BO1, half, h);
        float rawp = 0.f;
#pragma unroll
        for (int j = 0; j < 32; j++)
            rawp = fmaf(frelu(h[j]), sm[OFF_WO2 + cbase + j], rawp);
        float raw = rawp + __shfl_xor_sync(0xffffffffu, rawp, 1) + sm[OFF_MISC];

        float density = (raw > 0.f) ? (raw + log1pf(expf(-raw))) : log1pf(expf(raw));
        float delta = (fa - nr) / (float)NS;
        float am = expf(-delta * density);        // 1 - alpha

        // color head
        __syncthreads();                          // OFF_RAY ready
#pragma unroll
        for (int j = 0; j < 32; j++) e[j] += sm[OFF_RAY + cbase + j];
        dense_split(e, sm + OFF_WC1, sm + OFF_BC1, half, h);
        float c0p = 0.f, c1p = 0.f, c2p = 0.f;
#pragma unroll
        for (int j = 0; j < 32; j++) {
            float hv = frelu(h[j]);
            int gi = cbase + j;
            c0p = fmaf(hv, sm[OFF_WC2 + gi * 3 + 0], c0p);
            c1p = fmaf(hv, sm[OFF_WC2 + gi * 3 + 1], c1p);
            c2p = fmaf(hv, sm[OFF_WC2 + gi * 3 + 2], c2p);
        }
        float c0 = c0p + __shfl_xor_sync(0xffffffffu, c0p, 1) + sm[OFF_MISC + 1];
        float c1 = c1p + __shfl_xor_sync(0xffffffffu, c1p, 1) + sm[OFF_MISC + 2];
        float c2 = c2p + __shfl_xor_sync(0xffffffffu, c2p, 1) + sm[OFF_MISC + 3];
        c0 = 1.f / (1.f + expf(-c0));
        c1 = 1.f / (1.f + expf(-c1));
        c2 = 1.f / (1.f + expf(-c2));

        // publish per-sample values
        if (half == 0) {
            sm[OFF_AM + s] = am;
            sm[OFF_C0 + s] = c0;
            sm[OFF_C1 + s] = c1;
            sm[OFF_C2 + s] = c2;
        }
        __syncthreads();

        // ---- transmittance scan + composite (first 128 threads; sample = tid) ----
        if (tid < NS) {
            const int lane = tid & 31, warp = tid >> 5;
            float a = sm[OFF_AM + tid];
            float incl = a;
#pragma unroll
            for (int off = 1; off < 32; off <<= 1) {
                float n = __shfl_up_sync(0xffffffffu, incl, off);
                if (lane >= off) incl *= n;
            }
            float excl = __shfl_up_sync(0xffffffffu, incl, 1);
            if (lane == 0) excl = 1.f;
            if (lane == 31) sm[OFF_WTOT + warp] = incl;
            __syncwarp();
            // cross-warp combine needs warp totals from all 4 warps
            __threadfence_block();
        }
        __syncthreads();
        if (tid < NS) {
            const int lane = tid & 31, warp = tid >> 5;
            float a = sm[OFF_AM + tid];
            float incl = a;
#pragma unroll
            for (int off = 1; off < 32; off <<= 1) {
                float n = __shfl_up_sync(0xffffffffu, incl, off);
                if (lane >= off) incl *= n;
            }
            float excl = __shfl_up_sync(0xffffffffu, incl, 1);
            if (lane == 0) excl = 1.f;
            float w0 = sm[OFF_WTOT + 0], w1 = sm[OFF_WTOT + 1];
            float w2t = sm[OFF_WTOT + 2], w3 = sm[OFF_WTOT + 3];
            float pre = 1.f;
            if (warp > 0) pre *= w0;
            if (warp > 1) pre *= w1;
            if (warp > 2) pre *= w2t;
            float T = pre * excl;
            float total = w0 * w1 * w2t * w3;
            float wgt = T * (1.f - a);

            float r0 = wgt * sm[OFF_C0 + tid];
            float r1 = wgt * sm[OFF_C1 + tid];
            float r2 = wgt * sm[OFF_C2 + tid];
#pragma unroll
            for (int off = 16; off > 0; off >>= 1) {
                r0 += __shfl_down_sync(0xffffffffu, r0, off);
                r1 += __shfl_down_sync(0xffffffffu, r1, off);
                r2 += __shfl_down_sync(0xffffffffu, r2, off);
            }
            if (lane == 0) {
                sm[OFF_PART + warp * 3 + 0] = r0;
                sm[OFF_PART + warp * 3 + 1] = r1;
                sm[OFF_PART + warp * 3 + 2] = r2;
            }
            __syncwarp();
            if (tid == 0) {
                // ensure other warps' partials visible: rely on next sync; defer write
            }
            if (tid == 127) sm[OFF_WTOT + 0] = total;  // stash total (safe: scan done)
        }
        __syncthreads();
        if (tid == 0) {
            float s0 = 0.f, s1 = 0.f, s2 = 0.f;
#pragma unroll
            for (int w = 0; w < 4; w++) {
                s0 += sm[OFF_PART + w * 3 + 0];
                s1 += sm[OFF_PART + w * 3 + 1];
                s2 += sm[OFF_PART + w * 3 + 2];
            }
            out[ray * 3 + 0] = s0;
            out[ray * 3 + 1] = s1;
            out[ray * 3 + 2] = s2;
            out[NRAYS * 3 + ray] = 1.f - sm[OFF_WTOT + 0];   // mask
        }
        __syncthreads();
    }
}

extern "C" void kernel_launch(void* const* d_in, const int* in_sizes, int n_in,
                              void* d_out, int out_size) {
    const float* origins    = (const float*)d_in[0];
    const float* directions = (const float*)d_in[1];
    const float* nearv      = (const float*)d_in[2];
    const float* farv       = (const float*)d_in[3];
    const float* grid       = (const float*)d_in[4];
    const float* Wr  = (const float*)d_in[5];
    const float* br  = (const float*)d_in[6];
    const float* Wt1 = (const float*)d_in[7];
    const float* bt1 = (const float*)d_in[8];
    const float* Wt2 = (const float*)d_in[9];
    const float* bt2 = (const float*)d_in[10];
    const float* Wo1 = (const float*)d_in[11];
    const float* bo1 = (const float*)d_in[12];
    const float* Wo2 = (const float*)d_in[13];
    const float* bo2 = (const float*)d_in[14];
    const float* Wc1 = (const float*)d_in[15];
    const float* bc1 = (const float*)d_in[16];
    const float* Wc2 = (const float*)d_in[17];
    const float* bc2 = (const float*)d_in[18];
    float* out = (float*)d_out;

    cudaFuncSetAttribute(lightplane_kernel,
                         cudaFuncAttributeMaxDynamicSharedMemorySize, SMEM_BYTES);
    lightplane_kernel<<<NRAYS / RPB, NT, SMEM_BYTES>>>(
        origins, directions, nearv, farv, grid,
        Wr, br, Wt1, bt1, Wt2, bt2, Wo1, bo1, Wo2, bo2,
        Wc1, bc1, Wc2, bc2, out);
}

// round 10
// speedup vs baseline: 1.6079x; 1.6079x over previous
#include <cuda_runtime.h>
#include <math.h>

#define NRAYS 8192
#define NS    128
#define NC    32
#define NH    64
#define NG    128
#define RPB   8          // rays per block

// dynamic smem layout (float offsets) — identical to the R3 passing kernel
#define OFF_WT1   0        // 2048
#define OFF_WT2   2048     // 4096
#define OFF_WO1   6144     // 4096
#define OFF_WC1   10240    // 4096
#define OFF_WR    14336    // 1344
#define OFF_WO2   15680    // 64
#define OFF_WC2   15744    // 192
#define OFF_BT1   15936    // 64
#define OFF_BT2   16000    // 64
#define OFF_BO1   16064    // 64
#define OFF_BC1   16128    // 64
#define OFF_BR    16192    // 64
#define OFF_RAY   16256    // 64
#define OFF_HE    16320    // 21 (pad 24)
#define OFF_WTOT  16344    // 4
#define OFF_PART  16348    // 12
#define OFF_MISC  16360    // bo2(1)+bc2(3)
#define SMEM_FLOATS 16364
#define SMEM_BYTES (SMEM_FLOATS * 4)

__device__ __forceinline__ float frelu(float x) { return x > 0.f ? x : 0.f; }

__device__ __forceinline__ unsigned long long pack2(float a) {
    unsigned long long r;
    unsigned u = __float_as_uint(a);
    asm("mov.b64 %0, {%1, %1};" : "=l"(r) : "r"(u));
    return r;
}
__device__ __forceinline__ void fma2(unsigned long long& d,
                                     unsigned long long a,
                                     unsigned long long b) {
    asm("fma.rn.f32x2 %0, %1, %2, %0;" : "+l"(d) : "l"(a), "l"(b));
}
__device__ __forceinline__ void unpack2(unsigned long long v, float& lo, float& hi) {
    unsigned l, h;
    asm("mov.b64 {%0, %1}, %2;" : "=r"(l), "=r"(h) : "l"(v));
    lo = __uint_as_float(l);
    hi = __uint_as_float(h);
}

// 16 outputs of in[IN] @ W[IN,64] + b : quarter-width accumulator block.
// sWq points at the quarter's column offset inside row 0 (row stride NH floats);
// sbq at the quarter's bias; outq receives 16 floats.
template <int IN>
__device__ __forceinline__ void dense16(const float* in, const float* sWq,
                                        const float* sbq, float* outq) {
    unsigned long long acc[8];
    const ulonglong2* b2 = (const ulonglong2*)sbq;
#pragma unroll
    for (int o = 0; o < 4; o++) {
        ulonglong2 b = b2[o];
        acc[2 * o] = b.x;
        acc[2 * o + 1] = b.y;
    }
#pragma unroll
    for (int i = 0; i < IN; i++) {
        unsigned long long f2 = pack2(in[i]);
        const ulonglong2* w2 = (const ulonglong2*)(sWq + i * NH);
#pragma unroll
        for (int o = 0; o < 4; o++) {
            ulonglong2 w = w2[o];
            fma2(acc[2 * o], f2, w.x);
            fma2(acc[2 * o + 1], f2, w.y);
        }
    }
#pragma unroll
    for (int o = 0; o < 8; o++) unpack2(acc[o], outq[2 * o], outq[2 * o + 1]);
}

__global__ void __launch_bounds__(NS, 3)
lightplane_kernel(const float* __restrict__ origins,
                  const float* __restrict__ directions,
                  const float* __restrict__ nearv,
                  const float* __restrict__ farv,
                  const float* __restrict__ grid,
                  const float* __restrict__ Wr,  const float* __restrict__ br,
                  const float* __restrict__ Wt1, const float* __restrict__ bt1,
                  const float* __restrict__ Wt2, const float* __restrict__ bt2,
                  const float* __restrict__ Wo1, const float* __restrict__ bo1,
                  const float* __restrict__ Wo2, const float* __restrict__ bo2,
                  const float* __restrict__ Wc1, const float* __restrict__ bc1,
                  const float* __restrict__ Wc2, const float* __restrict__ bc2,
                  float* __restrict__ out) {
    extern __shared__ float sm[];
    const int tid = threadIdx.x;
    const int lane = tid & 31, warp = tid >> 5;

    // ---- stage all weights into shared (once per block) — R3 verbatim ----
    {
        const float4* g;
        float4* s;
        g = (const float4*)Wt1; s = (float4*)(sm + OFF_WT1);
        for (int i = tid; i < 512; i += NS) s[i] = g[i];
        g = (const float4*)Wt2; s = (float4*)(sm + OFF_WT2);
        for (int i = tid; i < 1024; i += NS) s[i] = g[i];
        g = (const float4*)Wo1; s = (float4*)(sm + OFF_WO1);
        for (int i = tid; i < 1024; i += NS) s[i] = g[i];
        g = (const float4*)Wc1; s = (float4*)(sm + OFF_WC1);
        for (int i = tid; i < 1024; i += NS) s[i] = g[i];
        g = (const float4*)Wr; s = (float4*)(sm + OFF_WR);
        for (int i = tid; i < 336; i += NS) s[i] = g[i];
        if (tid < 16)              ((float4*)(sm + OFF_WO2))[tid]      = ((const float4*)Wo2)[tid];
        if (tid < 48)              ((float4*)(sm + OFF_WC2))[tid]      = ((const float4*)Wc2)[tid];
        if (tid >= 48 && tid < 64) ((float4*)(sm + OFF_BT1))[tid - 48] = ((const float4*)bt1)[tid - 48];
        if (tid >= 64 && tid < 80) ((float4*)(sm + OFF_BT2))[tid - 64] = ((const float4*)bt2)[tid - 64];
        if (tid >= 80 && tid < 96) ((float4*)(sm + OFF_BO1))[tid - 80] = ((const float4*)bo1)[tid - 80];
        if (tid >= 96 && tid < 112)((float4*)(sm + OFF_BC1))[tid - 96] = ((const float4*)bc1)[tid - 96];
        if (tid >= 112 && tid < 128)((float4*)(sm + OFF_BR))[tid - 112]= ((const float4*)br)[tid - 112];
        if (tid == 16) sm[OFF_MISC] = bo2[0];
        if (tid >= 17 && tid < 20) sm[OFF_MISC + 1 + tid - 17] = bc2[tid - 17];
    }
    __syncthreads();

    for (int rr = 0; rr < RPB; rr++) {
        const int ray = blockIdx.x * RPB + rr;
        const float dx = directions[ray * 3 + 0];
        const float dy = directions[ray * 3 + 1];
        const float dz = directions[ray * 3 + 2];
        const float nr = nearv[ray];
        const float fa = farv[ray];
        const float ox = origins[ray * 3 + 0];
        const float oy = origins[ray * 3 + 1];
        const float oz = origins[ray * 3 + 2];

        // harmonic encoding of direction (per ray) — R3 verbatim
        if (tid < 9) {
            int f = tid / 3, d = tid % 3;
            float dv = (d == 0) ? dx : ((d == 1) ? dy : dz);
            float ang = dv * (float)(1 << f);
            sm[OFF_HE + tid]     = sinf(ang);
            sm[OFF_HE + 9 + tid] = cosf(ang);
        }
        if (tid >= 9 && tid < 12) {
            int d = tid - 9;
            sm[OFF_HE + 18 + d] = (d == 0) ? dx : ((d == 1) ? dy : dz);
        }
        __syncthreads();                      // sync1: HE ready
        if (tid < NH) {
            float a = sm[OFF_BR + tid];
#pragma unroll
            for (int k = 0; k < 21; k++)
                a = fmaf(sm[OFF_HE + k], sm[OFF_WR + k * NH + tid], a);
            sm[OFF_RAY + tid] = a;
        }

        // ---- per-sample work (thread = sample) ----
        const float t = nr + (fa - nr) * (((float)tid + 0.5f) / (float)NS);
        const float px = ox + t * dx;
        const float py = oy + t * dy;
        const float pz = oz + t * dz;

        // trilinear gather of 32-channel features (packed accumulation) — R3 verbatim
        float feats[NC];
        {
            unsigned long long fac[16];
#pragma unroll
            for (int q = 0; q < 16; q++) fac[q] = 0ull;
            const float scale = 0.5f * (float)(NG - 1);
            float cx = (px + 1.f) * scale;
            float cy = (py + 1.f) * scale;
            float cz = (pz + 1.f) * scale;
            float fx = cx - floorf(cx), fy = cy - floorf(cy), fz = cz - floorf(cz);
            int x0 = min(max((int)floorf(cx), 0), NG - 1);
            int y0 = min(max((int)floorf(cy), 0), NG - 1);
            int z0 = min(max((int)floorf(cz), 0), NG - 1);
            int x1 = min(x0 + 1, NG - 1);
            int y1 = min(y0 + 1, NG - 1);
            int z1 = min(z0 + 1, NG - 1);
            float wx[2] = {1.f - fx, fx};
            float wy[2] = {1.f - fy, fy};
            float wz[2] = {1.f - fz, fz};
            int xs[2] = {x0, x1}, ys[2] = {y0, y1}, zs[2] = {z0, z1};
#pragma unroll
            for (int a = 0; a < 2; a++)
#pragma unroll
                for (int b = 0; b < 2; b++)
#pragma unroll
                    for (int c = 0; c < 2; c++) {
                        unsigned long long wp = pack2(wx[a] * wy[b] * wz[c]);
                        const ulonglong2* g2 = (const ulonglong2*)(grid +
                            ((size_t)((zs[c] * NG + ys[b]) * NG + xs[a])) * NC);
#pragma unroll
                        for (int q = 0; q < 8; q++) {
                            ulonglong2 v = g2[q];
                            fma2(fac[2 * q], wp, v.x);
                            fma2(fac[2 * q + 1], wp, v.y);
                        }
                    }
#pragma unroll
            for (int q = 0; q < 16; q++) unpack2(fac[q], feats[2 * q], feats[2 * q + 1]);
        }

        // trunk layer 1: e1 = relu(feats@Wt1+bt1) — quarter-split
        float e1[NH];
#pragma unroll
        for (int q = 0; q < 4; q++)
            dense16<NC>(feats, sm + OFF_WT1 + q * 16, sm + OFF_BT1 + q * 16,
                        e1 + q * 16);
#pragma unroll
        for (int o = 0; o < NH; o++) e1[o] = frelu(e1[o]);

        // trunk layer 2: e = relu(e1@Wt2+bt2)
        float e[NH];
#pragma unroll
        for (int q = 0; q < 4; q++)
            dense16<NH>(e1, sm + OFF_WT2 + q * 16, sm + OFF_BT2 + q * 16,
                        e + q * 16);
#pragma unroll
        for (int o = 0; o < NH; o++) e[o] = frelu(e[o]);

        // opacity head (fused drain): raw = relu(e@Wo1+bo1) . Wo2 + bo2
        float raw = sm[OFF_MISC];
#pragma unroll
        for (int q = 0; q < 4; q++) {
            float hq[16];
            dense16<NH>(e, sm + OFF_WO1 + q * 16, sm + OFF_BO1 + q * 16, hq);
#pragma unroll
            for (int j = 0; j < 16; j++)
                raw = fmaf(frelu(hq[j]), sm[OFF_WO2 + q * 16 + j], raw);
        }

        float density = (raw > 0.f) ? (raw + log1pf(expf(-raw))) : log1pf(expf(raw));
        float delta = (fa - nr) / (float)NS;
        float am = expf(-delta * density);   // 1 - alpha

        // color head (fused drain)
        __syncthreads();                      // sync2: OFF_RAY ready
#pragma unroll
        for (int i = 0; i < NH; i++) e[i] += sm[OFF_RAY + i];
        float c0 = sm[OFF_MISC + 1], c1 = sm[OFF_MISC + 2], c2 = sm[OFF_MISC + 3];
#pragma unroll
        for (int q = 0; q < 4; q++) {
            float hq[16];
            dense16<NH>(e, sm + OFF_WC1 + q * 16, sm + OFF_BC1 + q * 16, hq);
#pragma unroll
            for (int j = 0; j < 16; j++) {
                float hv = frelu(hq[j]);
                int gi = q * 16 + j;
                c0 = fmaf(hv, sm[OFF_WC2 + gi * 3 + 0], c0);
                c1 = fmaf(hv, sm[OFF_WC2 + gi * 3 + 1], c1);
                c2 = fmaf(hv, sm[OFF_WC2 + gi * 3 + 2], c2);
            }
        }
        c0 = 1.f / (1.f + expf(-c0));
        c1 = 1.f / (1.f + expf(-c1));
        c2 = 1.f / (1.f + expf(-c2));

        // ---- parallel transmittance scan (warp shuffle) — R3 verbatim ----
        float incl = am;
#pragma unroll
        for (int off = 1; off < 32; off <<= 1) {
            float n = __shfl_up_sync(0xffffffffu, incl, off);
            if (lane >= off) incl *= n;
        }
        float excl = __shfl_up_sync(0xffffffffu, incl, 1);
        if (lane == 0) excl = 1.f;
        if (lane == 31) sm[OFF_WTOT + warp] = incl;
        __syncthreads();                      // sync3: warp totals ready
        float w0 = sm[OFF_WTOT + 0], w1 = sm[OFF_WTOT + 1];
        float w2t = sm[OFF_WTOT + 2], w3 = sm[OFF_WTOT + 3];
        float pre = 1.f;
        if (warp > 0) pre *= w0;
        if (warp > 1) pre *= w1;
        if (warp > 2) pre *= w2t;
        float T = pre * excl;                 // transmittance before this sample
        float total = w0 * w1 * w2t * w3;     // trans[:, -1]
        float wgt = T * (1.f - am);

        float r0 = wgt * c0, r1 = wgt * c1, r2 = wgt * c2;
#pragma unroll
        for (int off = 16; off > 0; off >>= 1) {
            r0 += __shfl_down_sync(0xffffffffu, r0, off);
            r1 += __shfl_down_sync(0xffffffffu, r1, off);
            r2 += __shfl_down_sync(0xffffffffu, r2, off);
        }
        if (lane == 0) {
            sm[OFF_PART + warp * 3 + 0] = r0;
            sm[OFF_PART + warp * 3 + 1] = r1;
            sm[OFF_PART + warp * 3 + 2] = r2;
        }
        __syncthreads();                      // sync4: partials ready
        if (tid == 0) {
            float s0 = 0.f, s1 = 0.f, s2 = 0.f;
#pragma unroll
            for (int w = 0; w < 4; w++) {
                s0 += sm[OFF_PART + w * 3 + 0];
                s1 += sm[OFF_PART + w * 3 + 1];
                s2 += sm[OFF_PART + w * 3 + 2];
            }
            out[ray * 3 + 0] = s0;
            out[ray * 3 + 1] = s1;
            out[ray * 3 + 2] = s2;
            out[NRAYS * 3 + ray] = 1.f - total;   // mask
        }
        __syncthreads();
    }
}

extern "C" void kernel_launch(void* const* d_in, const int* in_sizes, int n_in,
                              void* d_out, int out_size) {
    const float* origins    = (const float*)d_in[0];
    const float* directions = (const float*)d_in[1];
    const float* nearv      = (const float*)d_in[2];
    const float* farv       = (const float*)d_in[3];
    const float* grid       = (const float*)d_in[4];
    const float* Wr  = (const float*)d_in[5];
    const float* br  = (const float*)d_in[6];
    const float* Wt1 = (const float*)d_in[7];
    const float* bt1 = (const float*)d_in[8];
    const float* Wt2 = (const float*)d_in[9];
    const float* bt2 = (const float*)d_in[10];
    const float* Wo1 = (const float*)d_in[11];
    const float* bo1 = (const float*)d_in[12];
    const float* Wo2 = (const float*)d_in[13];
    const float* bo2 = (const float*)d_in[14];
    const float* Wc1 = (const float*)d_in[15];
    const float* bc1 = (const float*)d_in[16];
    const float* Wc2 = (const float*)d_in[17];
    const float* bc2 = (const float*)d_in[18];
    float* out = (float*)d_out;

    cudaFuncSetAttribute(lightplane_kernel,
                         cudaFuncAttributeMaxDynamicSharedMemorySize, SMEM_BYTES);
    lightplane_kernel<<<NRAYS / RPB, NS, SMEM_BYTES>>>(
        origins, directions, nearv, farv, grid,
        Wr, br, Wt1, bt1, Wt2, bt2, Wo1, bo1, Wo2, bo2,
        Wc1, bc1, Wc2, bc2, out);
}

// round 11
// speedup vs baseline: 2.5149x; 1.5641x over previous
#include <cuda_runtime.h>
#include <math.h>

#define NRAYS 8192
#define NS    128
#define NT    256
#define NC    32
#define NH    64
#define NG    128
#define RPB   8

// smem layout (float offsets)
#define SA    0        // A buffer: 64 rows x 128 samples = 8192
#define SW1   8192     // Wt1 32x64 = 2048
#define SW2   10240    // Wt2 64x64 = 4096
#define SW3   14336    // Wo1 64x64 = 4096
#define SW4   18432    // Wc1 64x64 = 4096
#define SWR   22528    // Wr 21x64 = 1344
#define SWO2  23872    // 64
#define SWC2  23936    // 192
#define SBT1  24128    // 64
#define SBT2  24192    // 64
#define SBO1  24256    // 64
#define SBC1  24320    // 64
#define SBR   24384    // 64
#define SRAY  24448    // 64
#define SHE   24512    // 24
#define SWTOT 24536    // 4
#define SPART 24540    // 12
#define SMISC 24552    // bo2(1)+bc2(3)
#define SPP   24556    // 3*1024 partials (opacity reuses first 1024)
#define SMEM_FLOATS 27628
#define SMEM_BYTES (SMEM_FLOATS * 4)

typedef unsigned long long u64;

__device__ __forceinline__ float frelu(float x) { return x > 0.f ? x : 0.f; }

__device__ __forceinline__ u64 pack2(float a) {
    u64 r;
    unsigned u = __float_as_uint(a);
    asm("mov.b64 %0, {%1, %1};" : "=l"(r) : "r"(u));
    return r;
}
__device__ __forceinline__ void fma2(u64& d, u64 a, u64 b) {
    asm("fma.rn.f32x2 %0, %1, %2, %0;" : "+l"(d) : "l"(a), "l"(b));
}
__device__ __forceinline__ void unpack2(u64 v, float& lo, float& hi) {
    unsigned l, h;
    asm("mov.b64 {%0, %1}, %2;" : "=r"(l), "=r"(h) : "l"(v));
    lo = __uint_as_float(l);
    hi = __uint_as_float(h);
}

// C-tile GEMM: thread (i = tid&31 -> samples 4i..4i+3, j = tid>>5 -> outputs 8j..8j+7)
// A rows in sm[SA + k*128 + s]; W in sm[Woff + k*64 + n]; bias sm[Boff + n].
// Produces relu'd cc[sample][out].
template <int K, bool ADDRE>
__device__ __forceinline__ void gemm_tile(float* sm, int i, int j,
                                          int Woff, int Boff, float cc[4][8]) {
    u64 acc[16];
    {
        const ulonglong2* bb = (const ulonglong2*)(sm + Boff + 8 * j);
        ulonglong2 b0 = bb[0], b1 = bb[1];
#pragma unroll
        for (int s = 0; s < 4; s++) {
            acc[4 * s + 0] = b0.x; acc[4 * s + 1] = b0.y;
            acc[4 * s + 2] = b1.x; acc[4 * s + 3] = b1.y;
        }
    }
#pragma unroll 4
    for (int k = 0; k < K; k++) {
        float4 a4 = *(const float4*)(sm + SA + k * 128 + 4 * i);
        if (ADDRE) {
            float re = sm[SRAY + k];
            a4.x += re; a4.y += re; a4.z += re; a4.w += re;
        }
        u64 aa0 = pack2(a4.x), aa1 = pack2(a4.y);
        u64 aa2 = pack2(a4.z), aa3 = pack2(a4.w);
        const ulonglong2* wp = (const ulonglong2*)(sm + Woff + k * 64 + 8 * j);
        ulonglong2 wA = wp[0], wB = wp[1];
        fma2(acc[0],  aa0, wA.x); fma2(acc[1],  aa0, wA.y);
        fma2(acc[2],  aa0, wB.x); fma2(acc[3],  aa0, wB.y);
        fma2(acc[4],  aa1, wA.x); fma2(acc[5],  aa1, wA.y);
        fma2(acc[6],  aa1, wB.x); fma2(acc[7],  aa1, wB.y);
        fma2(acc[8],  aa2, wA.x); fma2(acc[9],  aa2, wA.y);
        fma2(acc[10], aa2, wB.x); fma2(acc[11], aa2, wB.y);
        fma2(acc[12], aa3, wA.x); fma2(acc[13], aa3, wA.y);
        fma2(acc[14], aa3, wB.x); fma2(acc[15], aa3, wB.y);
    }
#pragma unroll
    for (int s = 0; s < 4; s++)
#pragma unroll
        for (int p = 0; p < 4; p++) {
            float lo, hi;
            unpack2(acc[4 * s + p], lo, hi);
            cc[s][2 * p]     = frelu(lo);
            cc[s][2 * p + 1] = frelu(hi);
        }
}

__global__ void __launch_bounds__(NT, 2)
lightplane_kernel(const float* __restrict__ origins,
                  const float* __restrict__ directions,
                  const float* __restrict__ nearv,
                  const float* __restrict__ farv,
                  const float* __restrict__ grid,
                  const float* __restrict__ Wr,  const float* __restrict__ br,
                  const float* __restrict__ Wt1, const float* __restrict__ bt1,
                  const float* __restrict__ Wt2, const float* __restrict__ bt2,
                  const float* __restrict__ Wo1, const float* __restrict__ bo1,
                  const float* __restrict__ Wo2, const float* __restrict__ bo2,
                  const float* __restrict__ Wc1, const float* __restrict__ bc1,
                  const float* __restrict__ Wc2, const float* __restrict__ bc2,
                  float* __restrict__ out) {
    extern __shared__ float sm[];
    const int tid = threadIdx.x;
    const int i = tid & 31;       // sample tile: samples 4i..4i+3
    const int j = tid >> 5;       // output tile: outputs 8j..8j+7

    // ---- stage weights ----
    {
        const float4* g;
        float4* s4;
        g = (const float4*)Wt1; s4 = (float4*)(sm + SW1);
        for (int x = tid; x < 512; x += NT) s4[x] = g[x];
        g = (const float4*)Wt2; s4 = (float4*)(sm + SW2);
        for (int x = tid; x < 1024; x += NT) s4[x] = g[x];
        g = (const float4*)Wo1; s4 = (float4*)(sm + SW3);
        for (int x = tid; x < 1024; x += NT) s4[x] = g[x];
        g = (const float4*)Wc1; s4 = (float4*)(sm + SW4);
        for (int x = tid; x < 1024; x += NT) s4[x] = g[x];
        g = (const float4*)Wr; s4 = (float4*)(sm + SWR);
        for (int x = tid; x < 336; x += NT) s4[x] = g[x];
        for (int x = tid; x < 192; x += NT) sm[SWC2 + x] = Wc2[x];
        if (tid < 64) {
            sm[SWO2 + tid] = Wo2[tid];
            sm[SBT1 + tid] = bt1[tid];
            sm[SBT2 + tid] = bt2[tid];
            sm[SBO1 + tid] = bo1[tid];
            sm[SBC1 + tid] = bc1[tid];
            sm[SBR + tid]  = br[tid];
        }
        if (tid == 64) sm[SMISC] = bo2[0];
        if (tid >= 65 && tid < 68) sm[SMISC + 1 + tid - 65] = bc2[tid - 65];
    }
    __syncthreads();

    for (int rr = 0; rr < RPB; rr++) {
        const int ray = blockIdx.x * RPB + rr;
        const float dx = directions[ray * 3 + 0];
        const float dy = directions[ray * 3 + 1];
        const float dz = directions[ray * 3 + 2];
        const float nr = nearv[ray];
        const float fa = farv[ray];
        const float ox = origins[ray * 3 + 0];
        const float oy = origins[ray * 3 + 1];
        const float oz = origins[ray * 3 + 2];

        // harmonic encoding -> SHE
        if (tid < 9) {
            int f = tid / 3, d = tid % 3;
            float dv = (d == 0) ? dx : ((d == 1) ? dy : dz);
            float ang = dv * (float)(1 << f);
            sm[SHE + tid]     = sinf(ang);
            sm[SHE + 9 + tid] = cosf(ang);
        }
        if (tid >= 9 && tid < 12) {
            int d = tid - 9;
            sm[SHE + 18 + d] = (d == 0) ? dx : ((d == 1) ? dy : dz);
        }
        __syncthreads();                    // SHE ready
        if (tid < NH) {
            float a = sm[SBR + tid];
#pragma unroll
            for (int k = 0; k < 21; k++)
                a = fmaf(sm[SHE + k], sm[SWR + k * NH + tid], a);
            sm[SRAY + tid] = a;
        }

        // ---- trilinear gather: thread t<128 = sample t, STS to A rows ----
        if (tid < NS) {
            const float t = nr + (fa - nr) * (((float)tid + 0.5f) / (float)NS);
            const float px = ox + t * dx;
            const float py = oy + t * dy;
            const float pz = oz + t * dz;
            float feats[NC];
            {
                u64 fac[16];
#pragma unroll
                for (int q = 0; q < 16; q++) fac[q] = 0ull;
                const float scale = 0.5f * (float)(NG - 1);
                float cx = (px + 1.f) * scale;
                float cy = (py + 1.f) * scale;
                float cz = (pz + 1.f) * scale;
                int x0 = min(max((int)floorf(cx), 0), NG - 1);
                int y0 = min(max((int)floorf(cy), 0), NG - 1);
                int z0 = min(max((int)floorf(cz), 0), NG - 1);
                int x1 = min(x0 + 1, NG - 1);
                int y1 = min(y0 + 1, NG - 1);
                int z1 = min(z0 + 1, NG - 1);
                float fx = cx - floorf(cx), fy = cy - floorf(cy), fz = cz - floorf(cz);
                float wx[2] = {1.f - fx, fx};
                float wy[2] = {1.f - fy, fy};
                float wz[2] = {1.f - fz, fz};
                int xs[2] = {x0, x1}, ys[2] = {y0, y1}, zs[2] = {z0, z1};
#pragma unroll
                for (int a = 0; a < 2; a++)
#pragma unroll
                    for (int b = 0; b < 2; b++)
#pragma unroll
                        for (int c = 0; c < 2; c++) {
                            u64 wp = pack2(wx[a] * wy[b] * wz[c]);
                            const ulonglong2* g2 = (const ulonglong2*)(grid +
                                ((size_t)((zs[c] * NG + ys[b]) * NG + xs[a])) * NC);
#pragma unroll
                            for (int q = 0; q < 8; q++) {
                                ulonglong2 v = g2[q];
                                fma2(fac[2 * q], wp, v.x);
                                fma2(fac[2 * q + 1], wp, v.y);
                            }
                        }
#pragma unroll
                for (int q = 0; q < 16; q++)
                    unpack2(fac[q], feats[2 * q], feats[2 * q + 1]);
            }
#pragma unroll
            for (int k = 0; k < NC; k++) sm[SA + k * 128 + tid] = feats[k];
        }
        __syncthreads();                    // A(feats), SRAY ready

        float cc[4][8];

        // ---- L1: 32 -> 64, relu, STS ----
        gemm_tile<NC, false>(sm, i, j, SW1, SBT1, cc);
        __syncthreads();                    // all reads of A done
#pragma unroll
        for (int o = 0; o < 8; o++) {
            float4 v = make_float4(cc[0][o], cc[1][o], cc[2][o], cc[3][o]);
            *(float4*)(sm + SA + (8 * j + o) * 128 + 4 * i) = v;
        }
        __syncthreads();

        // ---- L2: 64 -> 64, relu, STS (e) ----
        gemm_tile<NH, false>(sm, i, j, SW2, SBT2, cc);
        __syncthreads();
#pragma unroll
        for (int o = 0; o < 8; o++) {
            float4 v = make_float4(cc[0][o], cc[1][o], cc[2][o], cc[3][o]);
            *(float4*)(sm + SA + (8 * j + o) * 128 + 4 * i) = v;
        }
        __syncthreads();

        // ---- L3: opacity head GEMM + drain ----
        gemm_tile<NH, false>(sm, i, j, SW3, SBO1, cc);
#pragma unroll
        for (int s = 0; s < 4; s++) {
            float p = 0.f;
#pragma unroll
            for (int o = 0; o < 8; o++)
                p = fmaf(cc[s][o], sm[SWO2 + 8 * j + o], p);
            sm[SPP + j * 128 + 4 * i + s] = p;
        }
        __syncthreads();
        float am = 0.f;
        if (tid < NS) {
            float raw = sm[SMISC];
#pragma unroll
            for (int jj = 0; jj < 8; jj++) raw += sm[SPP + jj * 128 + tid];
            float density = (raw > 0.f) ? (raw + log1pf(expf(-raw)))
                                        : log1pf(expf(raw));
            float delta = (fa - nr) / (float)NS;
            am = expf(-delta * density);    // 1 - alpha
        }
        __syncthreads();                    // PP consumed before color reuse

        // ---- L4: color head GEMM (input e + ray_enc) + drain ----
        gemm_tile<NH, true>(sm, i, j, SW4, SBC1, cc);
#pragma unroll
        for (int c = 0; c < 3; c++) {
            float p0 = 0.f, p1 = 0.f, p2 = 0.f, p3 = 0.f;
#pragma unroll
            for (int o = 0; o < 8; o++) {
                float w = sm[SWC2 + (8 * j + o) * 3 + c];
                p0 = fmaf(cc[0][o], w, p0);
                p1 = fmaf(cc[1][o], w, p1);
                p2 = fmaf(cc[2][o], w, p2);
                p3 = fmaf(cc[3][o], w, p3);
            }
            sm[SPP + c * 1024 + j * 128 + 4 * i + 0] = p0;
            sm[SPP + c * 1024 + j * 128 + 4 * i + 1] = p1;
            sm[SPP + c * 1024 + j * 128 + 4 * i + 2] = p2;
            sm[SPP + c * 1024 + j * 128 + 4 * i + 3] = p3;
        }
        __syncthreads();
        float c0 = 0.f, c1 = 0.f, c2 = 0.f;
        if (tid < NS) {
            float a0 = sm[SMISC + 1], a1 = sm[SMISC + 2], a2 = sm[SMISC + 3];
#pragma unroll
            for (int jj = 0; jj < 8; jj++) {
                a0 += sm[SPP + 0 * 1024 + jj * 128 + tid];
                a1 += sm[SPP + 1 * 1024 + jj * 128 + tid];
                a2 += sm[SPP + 2 * 1024 + jj * 128 + tid];
            }
            c0 = 1.f / (1.f + expf(-a0));
            c1 = 1.f / (1.f + expf(-a1));
            c2 = 1.f / (1.f + expf(-a2));
        }

        // ---- transmittance scan + composite (threads 0..127, sample = tid) ----
        const int lane = tid & 31, warp = tid >> 5;
        float excl = 1.f;
        if (tid < NS) {
            float incl = am;
#pragma unroll
            for (int off = 1; off < 32; off <<= 1) {
                float n = __shfl_up_sync(0xffffffffu, incl, off);
                if (lane >= off) incl *= n;
            }
            excl = __shfl_up_sync(0xffffffffu, incl, 1);
            if (lane == 0) excl = 1.f;
            if (lane == 31) sm[SWTOT + warp] = incl;
        }
        __syncthreads();
        if (tid < NS) {
            float w0 = sm[SWTOT + 0], w1 = sm[SWTOT + 1];
            float w2t = sm[SWTOT + 2], w3 = sm[SWTOT + 3];
            float pre = 1.f;
            if (warp > 0) pre *= w0;
            if (warp > 1) pre *= w1;
            if (warp > 2) pre *= w2t;
            float T = pre * excl;
            float total = w0 * w1 * w2t * w3;
            float wgt = T * (1.f - am);

            float r0 = wgt * c0, r1 = wgt * c1, r2 = wgt * c2;
#pragma unroll
            for (int off = 16; off > 0; off >>= 1) {
                r0 += __shfl_down_sync(0xffffffffu, r0, off);
                r1 += __shfl_down_sync(0xffffffffu, r1, off);
                r2 += __shfl_down_sync(0xffffffffu, r2, off);
            }
            if (lane == 0) {
                sm[SPART + warp * 3 + 0] = r0;
                sm[SPART + warp * 3 + 1] = r1;
                sm[SPART + warp * 3 + 2] = r2;
            }
            if (tid == 127) sm[SWTOT + 0] = total;
        }
        __syncthreads();
        if (tid == 0) {
            float s0 = 0.f, s1 = 0.f, s2 = 0.f;
#pragma unroll
            for (int w = 0; w < 4; w++) {
                s0 += sm[SPART + w * 3 + 0];
                s1 += sm[SPART + w * 3 + 1];
                s2 += sm[SPART + w * 3 + 2];
            }
            out[ray * 3 + 0] = s0;
            out[ray * 3 + 1] = s1;
            out[ray * 3 + 2] = s2;
            out[NRAYS * 3 + ray] = 1.f - sm[SWTOT + 0];   // mask
        }
        __syncthreads();
    }
}

extern "C" void kernel_launch(void* const* d_in, const int* in_sizes, int n_in,
                              void* d_out, int out_size) {
    const float* origins    = (const float*)d_in[0];
    const float* directions = (const float*)d_in[1];
    const float* nearv      = (const float*)d_in[2];
    const float* farv       = (const float*)d_in[3];
    const float* grid       = (const float*)d_in[4];
    const float* Wr  = (const float*)d_in[5];
    const float* br  = (const float*)d_in[6];
    const float* Wt1 = (const float*)d_in[7];
    const float* bt1 = (const float*)d_in[8];
    const float* Wt2 = (const float*)d_in[9];
    const float* bt2 = (const float*)d_in[10];
    const float* Wo1 = (const float*)d_in[11];
    const float* bo1 = (const float*)d_in[12];
    const float* Wo2 = (const float*)d_in[13];
    const float* bo2 = (const float*)d_in[14];
    const float* Wc1 = (const float*)d_in[15];
    const float* bc1 = (const float*)d_in[16];
    const float* Wc2 = (const float*)d_in[17];
    const float* bc2 = (const float*)d_in[18];
    float* out = (float*)d_out;

    cudaFuncSetAttribute(lightplane_kernel,
                         cudaFuncAttributeMaxDynamicSharedMemorySize, SMEM_BYTES);
    lightplane_kernel<<<NRAYS / RPB, NT, SMEM_BYTES>>>(
        origins, directions, nearv, farv, grid,
        Wr, br, Wt1, bt1, Wt2, bt2, Wo1, bo1, Wo2, bo2,
        Wc1, bc1, Wc2, bc2, out);
}

// round 12
// speedup vs baseline: 3.4881x; 1.3870x over previous
#include <cuda_runtime.h>
#include <cuda_bf16.h>
#include <math.h>

#define NRAYS 8192
#define NS    128
#define NT    512
#define NC    32
#define NH    64
#define NG    128
#define RPB   8
#define KPAD  72   // bf16 elems per A/W row (144B)

// smem byte offsets
#define OB_AH   0
#define OB_AL   18432
#define OB_A2H  36864
#define OB_A2L  55296
#define OB_W    73728          // per layer: hi 9216B + lo 9216B
#define OB_MF   147456
// float offsets inside MF
#define MF_WR    0
#define MF_WO2   1344
#define MF_WC2   1408
#define MF_BT1   1600
#define MF_BT2   1664
#define MF_BO1   1728
#define MF_BC1   1792
#define MF_BR    1856
#define MF_RAY   1920
#define MF_HE    1984
#define MF_WTOT  2008
#define MF_PART  2012
#define MF_MISC  2024
#define MF_SPPC  2028          // 3*1024
#define MF_SPPO  5100          // 1024
#define MF_COUNT 6124
#define SMEM_BYTES (OB_MF + MF_COUNT * 4)

typedef unsigned long long u64;

__device__ __forceinline__ float frelu(float x) { return x > 0.f ? x : 0.f; }

__device__ __forceinline__ u64 pack2(float a) {
    u64 r;
    unsigned u = __float_as_uint(a);
    asm("mov.b64 %0, {%1, %1};" : "=l"(r) : "r"(u));
    return r;
}
__device__ __forceinline__ void fma2(u64& d, u64 a, u64 b) {
    asm("fma.rn.f32x2 %0, %1, %2, %0;" : "+l"(d) : "l"(a), "l"(b));
}
__device__ __forceinline__ void unpack2(u64 v, float& lo, float& hi) {
    unsigned l, h;
    asm("mov.b64 {%0, %1}, %2;" : "=r"(l), "=r"(h) : "l"(v));
    lo = __uint_as_float(l);
    hi = __uint_as_float(h);
}
__device__ __forceinline__ unsigned smem_u32(const void* p) {
    unsigned a;
    asm("{ .reg .u64 t; cvta.to.shared.u64 t, %1; cvt.u32.u64 %0, t; }"
        : "=r"(a) : "l"(p));
    return a;
}
// split pair (x0 even-k, x1 odd-k) into packed bf16 hi/lo words (low half = x0)
__device__ __forceinline__ void bsplit2(float x0, float x1, unsigned& h, unsigned& l) {
    asm("cvt.rn.bf16x2.f32 %0, %1, %2;" : "=r"(h) : "f"(x1), "f"(x0));
    float h0 = __uint_as_float(h << 16);
    float h1 = __uint_as_float(h & 0xFFFF0000u);
    asm("cvt.rn.bf16x2.f32 %0, %1, %2;" : "=r"(l) : "f"(x1 - h1), "f"(x0 - h0));
}
__device__ __forceinline__ void ldm4(unsigned& a0, unsigned& a1, unsigned& a2,
                                     unsigned& a3, unsigned addr) {
    asm volatile("ldmatrix.sync.aligned.m8n8.x4.shared.b16 {%0,%1,%2,%3}, [%4];"
                 : "=r"(a0), "=r"(a1), "=r"(a2), "=r"(a3) : "r"(addr));
}
__device__ __forceinline__ void mmab(float* d, unsigned a0, unsigned a1,
                                     unsigned a2, unsigned a3,
                                     unsigned b0, unsigned b1) {
    asm volatile("mma.sync.aligned.m16n8k16.row.col.f32.bf16.bf16.f32 "
                 "{%0,%1,%2,%3},{%4,%5,%6,%7},{%8,%9},{%0,%1,%2,%3};"
                 : "+f"(d[0]), "+f"(d[1]), "+f"(d[2]), "+f"(d[3])
                 : "r"(a0), "r"(a1), "r"(a2), "r"(a3), "r"(b0), "r"(b1));
}

// one layer GEMM for this warp: d[mt][4] += A[m0base..][*] @ W[*][n0..n0+7]
template <int KS>
__device__ __forceinline__ void mma_layer(
    unsigned aH, unsigned aL,                          // cvta smem byte addrs
    const unsigned short* wH, const unsigned short* wL,// element pointers
    int m0base, int n0, int lane, float d[4][4]) {
    const int g = lane >> 2, i = lane & 3;
    const int lr = lane & 15, kc = (lane >> 4) << 3;
#pragma unroll
    for (int mt = 0; mt < 4; mt++)
#pragma unroll
        for (int r = 0; r < 4; r++) d[mt][r] = 0.f;
#pragma unroll
    for (int ks = 0; ks < KS; ks++) {
        const int k0 = ks * 16;
        const int wb = (n0 + g) * KPAD + k0 + 2 * i;
        unsigned bh0 = *(const unsigned*)(wH + wb);
        unsigned bh1 = *(const unsigned*)(wH + wb + 8);
        unsigned bl0 = *(const unsigned*)(wL + wb);
        unsigned bl1 = *(const unsigned*)(wL + wb + 8);
#pragma unroll
        for (int mt = 0; mt < 4; mt++) {
            const int m0 = m0base + mt * 16;
            unsigned off = (unsigned)((m0 + lr) * KPAD + k0 + kc) * 2u;
            unsigned ah0, ah1, ah2, ah3, al0, al1, al2, al3;
            ldm4(ah0, ah1, ah2, ah3, aH + off);
            ldm4(al0, al1, al2, al3, aL + off);
            mmab(d[mt], ah0, ah1, ah2, ah3, bh0, bh1);
            mmab(d[mt], ah0, ah1, ah2, ah3, bl0, bl1);
            mmab(d[mt], al0, al1, al2, al3, bh0, bh1);
        }
    }
}

__global__ void __launch_bounds__(NT, 1)
lightplane_kernel(const float* __restrict__ origins,
                  const float* __restrict__ directions,
                  const float* __restrict__ nearv,
                  const float* __restrict__ farv,
                  const float* __restrict__ grid,
                  const float* __restrict__ Wr,  const float* __restrict__ br,
                  const float* __restrict__ Wt1, const float* __restrict__ bt1,
                  const float* __restrict__ Wt2, const float* __restrict__ bt2,
                  const float* __restrict__ Wo1, const float* __restrict__ bo1,
                  const float* __restrict__ Wo2, const float* __restrict__ bo2,
                  const float* __restrict__ Wc1, const float* __restrict__ bc1,
                  const float* __restrict__ Wc2, const float* __restrict__ bc2,
                  float* __restrict__ out) {
    extern __shared__ char smem[];
    float* mf = (float*)(smem + OB_MF);
    unsigned short* smW = (unsigned short*)(smem + OB_W);
    const int tid = threadIdx.x;
    const int lane = tid & 31, warp = tid >> 5;
    const int wm = warp >> 3, wn = warp & 7;
    const int n0 = wn * 8;
    const int m0base = wm * 64;
    const int g = lane >> 2, i = lane & 3;
    const unsigned aHB  = smem_u32(smem) + OB_AH;
    const unsigned aLB  = smem_u32(smem) + OB_AL;
    const unsigned a2HB = smem_u32(smem) + OB_A2H;
    const unsigned a2LB = smem_u32(smem) + OB_A2L;

    // ---- stage weights: transpose to [n][KPAD], bf16 hi/lo ----
    {
        const float* Ws[4] = {Wt1, Wt2, Wo1, Wc1};
        const int Ks[4] = {NC, NH, NH, NH};
#pragma unroll 1
        for (int L = 0; L < 4; L++) {
            unsigned short* wh = smW + L * 9216;
            unsigned short* wl = wh + 4608;
            const float* W = Ws[L];
            const int tot = Ks[L] * 64;
            for (int idx = tid; idx < tot; idx += NT) {
                int k = idx >> 6, n = idx & 63;
                float w = W[idx];
                __nv_bfloat16 hb = __float2bfloat16(w);
                float hf = __bfloat162float(hb);
                __nv_bfloat16 lb = __float2bfloat16(w - hf);
                wh[n * KPAD + k] = *(unsigned short*)&hb;
                wl[n * KPAD + k] = *(unsigned short*)&lb;
            }
        }
        for (int x = tid; x < 1344; x += NT) mf[MF_WR + x] = Wr[x];
        for (int x = tid; x < 192; x += NT) mf[MF_WC2 + x] = Wc2[x];
        if (tid < 64) {
            mf[MF_WO2 + tid] = Wo2[tid];
            mf[MF_BT1 + tid] = bt1[tid];
            mf[MF_BT2 + tid] = bt2[tid];
            mf[MF_BO1 + tid] = bo1[tid];
            mf[MF_BC1 + tid] = bc1[tid];
            mf[MF_BR + tid]  = br[tid];
        }
        if (tid == 64) mf[MF_MISC] = bo2[0];
        if (tid >= 65 && tid < 68) mf[MF_MISC + 1 + tid - 65] = bc2[tid - 65];
    }
    __syncthreads();

#pragma unroll 1
    for (int rr = 0; rr < RPB; rr++) {
        const int ray = blockIdx.x * RPB + rr;
        const float dx = directions[ray * 3 + 0];
        const float dy = directions[ray * 3 + 1];
        const float dz = directions[ray * 3 + 2];
        const float nr = nearv[ray];
        const float fa = farv[ray];
        const float ox = origins[ray * 3 + 0];
        const float oy = origins[ray * 3 + 1];
        const float oz = origins[ray * 3 + 2];

        if (tid < 9) {
            int f = tid / 3, d = tid % 3;
            float dv = (d == 0) ? dx : ((d == 1) ? dy : dz);
            float ang = dv * (float)(1 << f);
            mf[MF_HE + tid]     = sinf(ang);
            mf[MF_HE + 9 + tid] = cosf(ang);
        }
        if (tid >= 9 && tid < 12) {
            int d = tid - 9;
            mf[MF_HE + 18 + d] = (d == 0) ? dx : ((d == 1) ? dy : dz);
        }
        __syncthreads();                    // HE ready
        if (tid < NH) {
            float a = mf[MF_BR + tid];
#pragma unroll
            for (int k = 0; k < 21; k++)
                a = fmaf(mf[MF_HE + k], mf[MF_WR + k * NH + tid], a);
            mf[MF_RAY + tid] = a;
        }

        // ---- gather: 4 threads per sample, 8 channels each ----
        {
            const int m = tid >> 2, q = tid & 3;
            const float t = nr + (fa - nr) * (((float)m + 0.5f) / (float)NS);
            const float px = ox + t * dx;
            const float py = oy + t * dy;
            const float pz = oz + t * dz;
            u64 fac[4];
#pragma unroll
            for (int r = 0; r < 4; r++) fac[r] = 0ull;
            const float scale = 0.5f * (float)(NG - 1);
            float cx = (px + 1.f) * scale;
            float cy = (py + 1.f) * scale;
            float cz = (pz + 1.f) * scale;
            int x0 = min(max((int)floorf(cx), 0), NG - 1);
            int y0 = min(max((int)floorf(cy), 0), NG - 1);
            int z0 = min(max((int)floorf(cz), 0), NG - 1);
            int x1 = min(x0 + 1, NG - 1);
            int y1 = min(y0 + 1, NG - 1);
            int z1 = min(z0 + 1, NG - 1);
            float fx = cx - floorf(cx), fy = cy - floorf(cy), fz = cz - floorf(cz);
            float wx[2] = {1.f - fx, fx};
            float wy[2] = {1.f - fy, fy};
            float wz[2] = {1.f - fz, fz};
            int xs[2] = {x0, x1}, ys[2] = {y0, y1}, zs[2] = {z0, z1};
#pragma unroll
            for (int a = 0; a < 2; a++)
#pragma unroll
                for (int b = 0; b < 2; b++)
#pragma unroll
                    for (int c = 0; c < 2; c++) {
                        u64 wp = pack2(wx[a] * wy[b] * wz[c]);
                        const ulonglong2* g2 = (const ulonglong2*)(grid +
                            ((size_t)((zs[c] * NG + ys[b]) * NG + xs[a])) * NC + 8 * q);
                        ulonglong2 v0 = __ldg(&g2[0]);
                        fma2(fac[0], wp, v0.x);
                        fma2(fac[1], wp, v0.y);
                        ulonglong2 v1 = __ldg(&g2[1]);
                        fma2(fac[2], wp, v1.x);
                        fma2(fac[3], wp, v1.y);
                    }
#pragma unroll
            for (int r = 0; r < 4; r++) {
                float f0, f1;
                unpack2(fac[r], f0, f1);
                unsigned h, l;
                bsplit2(f0, f1, h, l);
                unsigned off = (unsigned)(m * KPAD + 8 * q + 2 * r) * 2u;
                *(unsigned*)(smem + OB_AH + off) = h;
                *(unsigned*)(smem + OB_AL + off) = l;
            }
        }
        __syncthreads();                    // A(feats), RAY ready

        float d[4][4];
        const int n = n0 + 2 * i;

        // ---- L1: K=32 ----
        mma_layer<2>(aHB, aLB, smW, smW + 4608, m0base, n0, lane, d);
        __syncthreads();                    // reads of A done
        {
            float b0 = mf[MF_BT1 + n], b1 = mf[MF_BT1 + n + 1];
#pragma unroll
            for (int mt = 0; mt < 4; mt++) {
                int r0 = m0base + mt * 16 + g;
                unsigned h, l;
                bsplit2(frelu(d[mt][0] + b0), frelu(d[mt][1] + b1), h, l);
                unsigned off = (unsigned)(r0 * KPAD + n) * 2u;
                *(unsigned*)(smem + OB_AH + off) = h;
                *(unsigned*)(smem + OB_AL + off) = l;
                bsplit2(frelu(d[mt][2] + b0), frelu(d[mt][3] + b1), h, l);
                off = (unsigned)((r0 + 8) * KPAD + n) * 2u;
                *(unsigned*)(smem + OB_AH + off) = h;
                *(unsigned*)(smem + OB_AL + off) = l;
            }
        }
        __syncthreads();

        // ---- L2: K=64; writes A (e) and A2 (e + ray_enc) ----
        mma_layer<4>(aHB, aLB, smW + 9216, smW + 13824, m0base, n0, lane, d);
        __syncthreads();
        {
            float b0 = mf[MF_BT2 + n], b1 = mf[MF_BT2 + n + 1];
            float r0v = mf[MF_RAY + n], r1v = mf[MF_RAY + n + 1];
#pragma unroll
            for (int mt = 0; mt < 4; mt++) {
                int r0 = m0base + mt * 16 + g;
                float v00 = frelu(d[mt][0] + b0), v01 = frelu(d[mt][1] + b1);
                float v10 = frelu(d[mt][2] + b0), v11 = frelu(d[mt][3] + b1);
                unsigned h, l;
                unsigned off = (unsigned)(r0 * KPAD + n) * 2u;
                bsplit2(v00, v01, h, l);
                *(unsigned*)(smem + OB_AH + off) = h;
                *(unsigned*)(smem + OB_AL + off) = l;
                bsplit2(v00 + r0v, v01 + r1v, h, l);
                *(unsigned*)(smem + OB_A2H + off) = h;
                *(unsigned*)(smem + OB_A2L + off) = l;
                off = (unsigned)((r0 + 8) * KPAD + n) * 2u;
                bsplit2(v10, v11, h, l);
                *(unsigned*)(smem + OB_AH + off) = h;
                *(unsigned*)(smem + OB_AL + off) = l;
                bsplit2(v10 + r0v, v11 + r1v, h, l);
                *(unsigned*)(smem + OB_A2H + off) = h;
                *(unsigned*)(smem + OB_A2L + off) = l;
            }
        }
        __syncthreads();

        // ---- L3: opacity head ----
        mma_layer<4>(aHB, aLB, smW + 18432, smW + 23040, m0base, n0, lane, d);
        {
            float b0 = mf[MF_BO1 + n], b1 = mf[MF_BO1 + n + 1];
            float w0 = mf[MF_WO2 + n], w1 = mf[MF_WO2 + n + 1];
#pragma unroll
            for (int mt = 0; mt < 4; mt++) {
                int r0 = m0base + mt * 16 + g;
                float pg  = frelu(d[mt][0] + b0) * w0 + frelu(d[mt][1] + b1) * w1;
                float pg8 = frelu(d[mt][2] + b0) * w0 + frelu(d[mt][3] + b1) * w1;
                pg  += __shfl_xor_sync(0xffffffffu, pg, 1);
                pg  += __shfl_xor_sync(0xffffffffu, pg, 2);
                pg8 += __shfl_xor_sync(0xffffffffu, pg8, 1);
                pg8 += __shfl_xor_sync(0xffffffffu, pg8, 2);
                if (i == 0) {
                    mf[MF_SPPO + wn * 128 + r0] = pg;
                    mf[MF_SPPO + wn * 128 + r0 + 8] = pg8;
                }
            }
        }

        // ---- L4: color head (reads A2) ----
        mma_layer<4>(a2HB, a2LB, smW + 27648, smW + 32256, m0base, n0, lane, d);
        {
            float b0 = mf[MF_BC1 + n], b1 = mf[MF_BC1 + n + 1];
#pragma unroll
            for (int mt = 0; mt < 4; mt++) {
                int r0 = m0base + mt * 16 + g;
                float h00 = frelu(d[mt][0] + b0), h01 = frelu(d[mt][1] + b1);
                float h10 = frelu(d[mt][2] + b0), h11 = frelu(d[mt][3] + b1);
#pragma unroll
                for (int c = 0; c < 3; c++) {
                    float wc0 = mf[MF_WC2 + n * 3 + c];
                    float wc1 = mf[MF_WC2 + (n + 1) * 3 + c];
                    float pg  = h00 * wc0 + h01 * wc1;
                    float pg8 = h10 * wc0 + h11 * wc1;
                    pg  += __shfl_xor_sync(0xffffffffu, pg, 1);
                    pg  += __shfl_xor_sync(0xffffffffu, pg, 2);
                    pg8 += __shfl_xor_sync(0xffffffffu, pg8, 1);
                    pg8 += __shfl_xor_sync(0xffffffffu, pg8, 2);
                    if (i == 0) {
                        mf[MF_SPPC + c * 1024 + wn * 128 + r0] = pg;
                        mf[MF_SPPC + c * 1024 + wn * 128 + r0 + 8] = pg8;
                    }
                }
            }
        }
        __syncthreads();

        // ---- per-sample finalize (threads 0..127) ----
        float am = 0.f, c0 = 0.f, c1 = 0.f, c2 = 0.f;
        if (tid < NS) {
            float raw = mf[MF_MISC];
            float a0 = mf[MF_MISC + 1], a1 = mf[MF_MISC + 2], a2 = mf[MF_MISC + 3];
#pragma unroll
            for (int w = 0; w < 8; w++) {
                raw += mf[MF_SPPO + w * 128 + tid];
                a0  += mf[MF_SPPC + 0 * 1024 + w * 128 + tid];
                a1  += mf[MF_SPPC + 1 * 1024 + w * 128 + tid];
                a2  += mf[MF_SPPC + 2 * 1024 + w * 128 + tid];
            }
            float density = (raw > 0.f) ? (raw + log1pf(expf(-raw)))
                                        : log1pf(expf(raw));
            float delta = (fa - nr) / (float)NS;
            am = expf(-delta * density);
            c0 = 1.f / (1.f + expf(-a0));
            c1 = 1.f / (1.f + expf(-a1));
            c2 = 1.f / (1.f + expf(-a2));
        }

        // ---- transmittance scan + composite ----
        float excl = 1.f;
        if (tid < NS) {
            float incl = am;
#pragma unroll
            for (int off = 1; off < 32; off <<= 1) {
                float nn = __shfl_up_sync(0xffffffffu, incl, off);
                if (lane >= off) incl *= nn;
            }
            excl = __shfl_up_sync(0xffffffffu, incl, 1);
            if (lane == 0) excl = 1.f;
            if (lane == 31) mf[MF_WTOT + warp] = incl;
        }
        __syncthreads();
        if (tid < NS) {
            float w0 = mf[MF_WTOT + 0], w1 = mf[MF_WTOT + 1];
            float w2t = mf[MF_WTOT + 2], w3 = mf[MF_WTOT + 3];
            float pre = 1.f;
            if (warp > 0) pre *= w0;
            if (warp > 1) pre *= w1;
            if (warp > 2) pre *= w2t;
            float T = pre * excl;
            float total = w0 * w1 * w2t * w3;
            float wgt = T * (1.f - am);
            float r0 = wgt * c0, r1 = wgt * c1, r2 = wgt * c2;
#pragma unroll
            for (int off = 16; off > 0; off >>= 1) {
                r0 += __shfl_down_sync(0xffffffffu, r0, off);
                r1 += __shfl_down_sync(0xffffffffu, r1, off);
                r2 += __shfl_down_sync(0xffffffffu, r2, off);
            }
            if (lane == 0) {
                mf[MF_PART + warp * 3 + 0] = r0;
                mf[MF_PART + warp * 3 + 1] = r1;
                mf[MF_PART + warp * 3 + 2] = r2;
            }
            if (tid == 127) mf[MF_WTOT + 0] = total;
        }
        __syncthreads();
        if (tid == 0) {
            float s0 = 0.f, s1 = 0.f, s2 = 0.f;
#pragma unroll
            for (int w = 0; w < 4; w++) {
                s0 += mf[MF_PART + w * 3 + 0];
                s1 += mf[MF_PART + w * 3 + 1];
                s2 += mf[MF_PART + w * 3 + 2];
            }
            out[ray * 3 + 0] = s0;
            out[ray * 3 + 1] = s1;
            out[ray * 3 + 2] = s2;
            out[NRAYS * 3 + ray] = 1.f - mf[MF_WTOT + 0];
        }
        __syncthreads();
    }
}

extern "C" void kernel_launch(void* const* d_in, const int* in_sizes, int n_in,
                              void* d_out, int out_size) {
    const float* origins    = (const float*)d_in[0];
    const float* directions = (const float*)d_in[1];
    const float* nearv      = (const float*)d_in[2];
    const float* farv       = (const float*)d_in[3];
    const float* grid       = (const float*)d_in[4];
    const float* Wr  = (const float*)d_in[5];
    const float* br  = (const float*)d_in[6];
    const float* Wt1 = (const float*)d_in[7];
    const float* bt1 = (const float*)d_in[8];
    const float* Wt2 = (const float*)d_in[9];
    const float* bt2 = (const float*)d_in[10];
    const float* Wo1 = (const float*)d_in[11];
    const float* bo1 = (const float*)d_in[12];
    const float* Wo2 = (const float*)d_in[13];
    const float* bo2 = (const float*)d_in[14];
    const float* Wc1 = (const float*)d_in[15];
    const float* bc1 = (const float*)d_in[16];
    const float* Wc2 = (const float*)d_in[17];
    const float* bc2 = (const float*)d_in[18];
    float* out = (float*)d_out;

    cudaFuncSetAttribute(lightplane_kernel,
                         cudaFuncAttributeMaxDynamicSharedMemorySize, SMEM_BYTES);
    lightplane_kernel<<<NRAYS / RPB, NT, SMEM_BYTES>>>(
        origins, directions, nearv, farv, grid,
        Wr, br, Wt1, bt1, Wt2, bt2, Wo1, bo1, Wo2, bo2,
        Wc1, bc1, Wc2, bc2, out);
}

// round 15
// speedup vs baseline: 4.1902x; 1.2013x over previous
#include <cuda_runtime.h>
#include <cuda_bf16.h>
#include <math.h>

#define NRAYS 8192
#define NS    128
#define NT    256
#define NC    32
#define NH    64
#define NG    128
#define RPB   8
#define KPAD  72   // bf16 elems per A/W row (144B)

// smem byte offsets
#define OB_AH   0
#define OB_AL   18432
#define OB_W    36864          // 4 layers x 18432 B (hi 9216 + lo 9216) -> ends 110592
#define OB_MF   110592
// float offsets inside MF
#define MF_WO2   0
#define MF_WC2   64
#define MF_BT1   256
#define MF_BT2   320
#define MF_BO1   384
#define MF_BC1   448
#define MF_BR    512
#define MF_RAY   576
#define MF_HE    640
#define MF_WTOT  664
#define MF_PART  668
#define MF_MISC  680
#define MF_SPPO  684           // 4*128 = 512
#define MF_COUNT 1196
#define SMEM_BYTES (OB_MF + MF_COUNT * 4)
// SPPC (3*512 floats = 6144 B) aliases the A buffer (dead after L4 mma)

typedef unsigned long long u64;

__device__ __forceinline__ float frelu(float x) { return x > 0.f ? x : 0.f; }

__device__ __forceinline__ u64 pack2(float a) {
    u64 r;
    unsigned u = __float_as_uint(a);
    asm("mov.b64 %0, {%1, %1};" : "=l"(r) : "r"(u));
    return r;
}
__device__ __forceinline__ void fma2(u64& d, u64 a, u64 b) {
    asm("fma.rn.f32x2 %0, %1, %2, %0;" : "+l"(d) : "l"(a), "l"(b));
}
__device__ __forceinline__ void unpack2(u64 v, float& lo, float& hi) {
    unsigned l, h;
    asm("mov.b64 {%0, %1}, %2;" : "=r"(l), "=r"(h) : "l"(v));
    lo = __uint_as_float(l);
    hi = __uint_as_float(h);
}
__device__ __forceinline__ unsigned smem_u32(const void* p) {
    unsigned a;
    asm("{ .reg .u64 t; cvta.to.shared.u64 t, %1; cvt.u32.u64 %0, t; }"
        : "=r"(a) : "l"(p));
    return a;
}
// split pair (x0 even-k, x1 odd-k) into packed bf16 hi/lo words (low half = x0)
__device__ __forceinline__ void bsplit2(float x0, float x1, unsigned& h, unsigned& l) {
    asm("cvt.rn.bf16x2.f32 %0, %1, %2;" : "=r"(h) : "f"(x1), "f"(x0));
    float h0 = __uint_as_float(h << 16);
    float h1 = __uint_as_float(h & 0xFFFF0000u);
    asm("cvt.rn.bf16x2.f32 %0, %1, %2;" : "=r"(l) : "f"(x1 - h1), "f"(x0 - h0));
}
__device__ __forceinline__ void ldm4(unsigned& a0, unsigned& a1, unsigned& a2,
                                     unsigned& a3, unsigned addr) {
    asm volatile("ldmatrix.sync.aligned.m8n8.x4.shared.b16 {%0,%1,%2,%3}, [%4];"
                 : "=r"(a0), "=r"(a1), "=r"(a2), "=r"(a3) : "r"(addr));
}
__device__ __forceinline__ void mmab(float* d, unsigned a0, unsigned a1,
                                     unsigned a2, unsigned a3,
                                     unsigned b0, unsigned b1) {
    asm volatile("mma.sync.aligned.m16n8k16.row.col.f32.bf16.bf16.f32 "
                 "{%0,%1,%2,%3},{%4,%5,%6,%7},{%8,%9},{%0,%1,%2,%3};"
                 : "+f"(d[0]), "+f"(d[1]), "+f"(d[2]), "+f"(d[3])
                 : "r"(a0), "r"(a1), "r"(a2), "r"(a3), "r"(b0), "r"(b1));
}

// Layer GEMM, warp covers rows [m0base, m0base+64), cols [n0, n0+16).
// A tiles loaded once, reused across both n-groups.
template <int KS>
__device__ __forceinline__ void mma_layer(
    unsigned aH, unsigned aL,
    const unsigned short* wH, const unsigned short* wL,
    int m0base, int n0, int lane, float d[4][2][4]) {
    const int g = lane >> 2, i = lane & 3;
    const int lr = lane & 15, kc = (lane >> 4) << 3;
#pragma unroll
    for (int mt = 0; mt < 4; mt++)
#pragma unroll
        for (int ng = 0; ng < 2; ng++)
#pragma unroll
            for (int r = 0; r < 4; r++) d[mt][ng][r] = 0.f;
#pragma unroll
    for (int ks = 0; ks < KS; ks++) {
        const int k0 = ks * 16;
        unsigned bh[2][2], bl[2][2];
#pragma unroll
        for (int ng = 0; ng < 2; ng++) {
            const int wb = (n0 + 8 * ng + g) * KPAD + k0 + 2 * i;
            bh[ng][0] = *(const unsigned*)(wH + wb);
            bh[ng][1] = *(const unsigned*)(wH + wb + 8);
            bl[ng][0] = *(const unsigned*)(wL + wb);
            bl[ng][1] = *(const unsigned*)(wL + wb + 8);
        }
#pragma unroll
        for (int mt = 0; mt < 4; mt++) {
            unsigned off = (unsigned)((m0base + mt * 16 + lr) * KPAD + k0 + kc) * 2u;
            unsigned ah0, ah1, ah2, ah3, al0, al1, al2, al3;
            ldm4(ah0, ah1, ah2, ah3, aH + off);
            ldm4(al0, al1, al2, al3, aL + off);
#pragma unroll
            for (int ng = 0; ng < 2; ng++) {
                mmab(d[mt][ng], ah0, ah1, ah2, ah3, bh[ng][0], bh[ng][1]);
                mmab(d[mt][ng], ah0, ah1, ah2, ah3, bl[ng][0], bl[ng][1]);
                mmab(d[mt][ng], al0, al1, al2, al3, bh[ng][0], bh[ng][1]);
            }
        }
    }
}

__global__ void __launch_bounds__(NT, 2)
lightplane_kernel(const float* __restrict__ origins,
                  const float* __restrict__ directions,
                  const float* __restrict__ nearv,
                  const float* __restrict__ farv,
                  const float* __restrict__ grid,
                  const float* __restrict__ Wr,  const float* __restrict__ br,
                  const float* __restrict__ Wt1, const float* __restrict__ bt1,
                  const float* __restrict__ Wt2, const float* __restrict__ bt2,
                  const float* __restrict__ Wo1, const float* __restrict__ bo1,
                  const float* __restrict__ Wo2, const float* __restrict__ bo2,
                  const float* __restrict__ Wc1, const float* __restrict__ bc1,
                  const float* __restrict__ Wc2, const float* __restrict__ bc2,
                  float* __restrict__ out) {
    extern __shared__ char smem[];
    float* mf = (float*)(smem + OB_MF);
    float* sppc = (float*)smem;            // aliases A buffer (safe post-L4)
    unsigned short* smW = (unsigned short*)(smem + OB_W);
    const int tid = threadIdx.x;
    const int lane = tid & 31, warp = tid >> 5;
    const int wm = warp >> 2, wn = warp & 3;
    const int n0 = wn * 16;
    const int m0base = wm * 64;
    const int g = lane >> 2, i = lane & 3;
    const unsigned aHB = smem_u32(smem) + OB_AH;
    const unsigned aLB = smem_u32(smem) + OB_AL;

    // ---- stage weights: transpose to [n][KPAD], bf16 hi/lo ----
    {
        const float* Ws[4] = {Wt1, Wt2, Wo1, Wc1};
        const int Ks[4] = {NC, NH, NH, NH};
#pragma unroll 1
        for (int L = 0; L < 4; L++) {
            unsigned short* wh = smW + L * 9216;
            unsigned short* wl = wh + 4608;
            const float* W = Ws[L];
            const int tot = Ks[L] * 64;
            for (int idx = tid; idx < tot; idx += NT) {
                int k = idx >> 6, n = idx & 63;
                float w = W[idx];
                __nv_bfloat16 hb = __float2bfloat16(w);
                float hf = __bfloat162float(hb);
                __nv_bfloat16 lb = __float2bfloat16(w - hf);
                wh[n * KPAD + k] = *(unsigned short*)&hb;
                wl[n * KPAD + k] = *(unsigned short*)&lb;
            }
        }
        for (int x = tid; x < 192; x += NT) mf[MF_WC2 + x] = Wc2[x];
        if (tid < 64) {
            mf[MF_WO2 + tid] = Wo2[tid];
            mf[MF_BT1 + tid] = bt1[tid];
            mf[MF_BT2 + tid] = bt2[tid];
            mf[MF_BO1 + tid] = bo1[tid];
            mf[MF_BC1 + tid] = bc1[tid];
            mf[MF_BR + tid]  = br[tid];
        }
        if (tid == 64) mf[MF_MISC] = bo2[0];
        if (tid >= 65 && tid < 68) mf[MF_MISC + 1 + tid - 65] = bc2[tid - 65];
    }
    __syncthreads();

#pragma unroll 1
    for (int rr = 0; rr < RPB; rr++) {
        const int ray = blockIdx.x * RPB + rr;
        const float dx = directions[ray * 3 + 0];
        const float dy = directions[ray * 3 + 1];
        const float dz = directions[ray * 3 + 2];
        const float nr = nearv[ray];
        const float fa = farv[ray];
        const float ox = origins[ray * 3 + 0];
        const float oy = origins[ray * 3 + 1];
        const float oz = origins[ray * 3 + 2];

        if (tid < 9) {
            int f = tid / 3, d = tid % 3;
            float dv = (d == 0) ? dx : ((d == 1) ? dy : dz);
            float ang = dv * (float)(1 << f);
            mf[MF_HE + tid]     = sinf(ang);
            mf[MF_HE + 9 + tid] = cosf(ang);
        }
        if (tid >= 9 && tid < 12) {
            int d = tid - 9;
            mf[MF_HE + 18 + d] = (d == 0) ? dx : ((d == 1) ? dy : dz);
        }
        __syncthreads();                    // HE ready
        if (tid < NH) {
            float a = mf[MF_BR + tid];
#pragma unroll
            for (int k = 0; k < 21; k++)
                a = fmaf(mf[MF_HE + k], __ldg(&Wr[k * NH + tid]), a);
            mf[MF_RAY + tid] = a;
        }

        // ---- gather: 2 threads per sample, 16 channels each ----
        {
            const int m = tid >> 1, q = tid & 1;
            const float t = nr + (fa - nr) * (((float)m + 0.5f) / (float)NS);
            const float px = ox + t * dx;
            const float py = oy + t * dy;
            const float pz = oz + t * dz;
            u64 fac[8];
#pragma unroll
            for (int r = 0; r < 8; r++) fac[r] = 0ull;
            const float scale = 0.5f * (float)(NG - 1);
            float cx = (px + 1.f) * scale;
            float cy = (py + 1.f) * scale;
            float cz = (pz + 1.f) * scale;
            int x0 = min(max((int)floorf(cx), 0), NG - 1);
            int y0 = min(max((int)floorf(cy), 0), NG - 1);
            int z0 = min(max((int)floorf(cz), 0), NG - 1);
            int x1 = min(x0 + 1, NG - 1);
            int y1 = min(y0 + 1, NG - 1);
            int z1 = min(z0 + 1, NG - 1);
            float fx = cx - floorf(cx), fy = cy - floorf(cy), fz = cz - floorf(cz);
            float wx[2] = {1.f - fx, fx};
            float wy[2] = {1.f - fy, fy};
            float wz[2] = {1.f - fz, fz};
            int xs[2] = {x0, x1}, ys[2] = {y0, y1}, zs[2] = {z0, z1};
#pragma unroll
            for (int a = 0; a < 2; a++)
#pragma unroll
                for (int b = 0; b < 2; b++)
#pragma unroll
                    for (int c = 0; c < 2; c++) {
                        u64 wp = pack2(wx[a] * wy[b] * wz[c]);
                        const ulonglong2* g2 = (const ulonglong2*)(grid +
                            ((size_t)((zs[c] * NG + ys[b]) * NG + xs[a])) * NC + 16 * q);
#pragma unroll
                        for (int q4 = 0; q4 < 4; q4++) {
                            ulonglong2 v = __ldg(&g2[q4]);
                            fma2(fac[2 * q4], wp, v.x);
                            fma2(fac[2 * q4 + 1], wp, v.y);
                        }
                    }
#pragma unroll
            for (int r = 0; r < 8; r++) {
                float f0, f1;
                unpack2(fac[r], f0, f1);
                unsigned h, l;
                bsplit2(f0, f1, h, l);
                unsigned off = (unsigned)(m * KPAD + 16 * q + 2 * r) * 2u;
                *(unsigned*)(smem + OB_AH + off) = h;
                *(unsigned*)(smem + OB_AL + off) = l;
            }
        }
        __syncthreads();                    // A(feats), RAY ready

        float d[4][2][4];

        // ---- L1: K=32 ----
        mma_layer<2>(aHB, aLB, smW, smW + 4608, m0base, n0, lane, d);
        __syncthreads();                    // reads of A done
#pragma unroll
        for (int mt = 0; mt < 4; mt++)
#pragma unroll
            for (int ng = 0; ng < 2; ng++) {
                const int n = n0 + 8 * ng + 2 * i;
                float b0 = mf[MF_BT1 + n], b1 = mf[MF_BT1 + n + 1];
                int r0 = m0base + mt * 16 + g;
                unsigned h, l;
                bsplit2(frelu(d[mt][ng][0] + b0), frelu(d[mt][ng][1] + b1), h, l);
                unsigned off = (unsigned)(r0 * KPAD + n) * 2u;
                *(unsigned*)(smem + OB_AH + off) = h;
                *(unsigned*)(smem + OB_AL + off) = l;
                bsplit2(frelu(d[mt][ng][2] + b0), frelu(d[mt][ng][3] + b1), h, l);
                off = (unsigned)((r0 + 8) * KPAD + n) * 2u;
                *(unsigned*)(smem + OB_AH + off) = h;
                *(unsigned*)(smem + OB_AL + off) = l;
            }
        __syncthreads();

        // ---- L2: K=64 -> e ----
        mma_layer<4>(aHB, aLB, smW + 9216, smW + 13824, m0base, n0, lane, d);
        __syncthreads();
#pragma unroll
        for (int mt = 0; mt < 4; mt++)
#pragma unroll
            for (int ng = 0; ng < 2; ng++) {
                const int n = n0 + 8 * ng + 2 * i;
                float b0 = mf[MF_BT2 + n], b1 = mf[MF_BT2 + n + 1];
                int r0 = m0base + mt * 16 + g;
                unsigned h, l;
                bsplit2(frelu(d[mt][ng][0] + b0), frelu(d[mt][ng][1] + b1), h, l);
                unsigned off = (unsigned)(r0 * KPAD + n) * 2u;
                *(unsigned*)(smem + OB_AH + off) = h;
                *(unsigned*)(smem + OB_AL + off) = l;
                bsplit2(frelu(d[mt][ng][2] + b0), frelu(d[mt][ng][3] + b1), h, l);
                off = (unsigned)((r0 + 8) * KPAD + n) * 2u;
                *(unsigned*)(smem + OB_AH + off) = h;
                *(unsigned*)(smem + OB_AL + off) = l;
            }
        __syncthreads();

        // ---- L3: opacity head (reads A=e) ----
        mma_layer<4>(aHB, aLB, smW + 18432, smW + 23040, m0base, n0, lane, d);
#pragma unroll
        for (int mt = 0; mt < 4; mt++) {
            int r0 = m0base + mt * 16 + g;
            float pg = 0.f, pg8 = 0.f;
#pragma unroll
            for (int ng = 0; ng < 2; ng++) {
                const int n = n0 + 8 * ng + 2 * i;
                float b0 = mf[MF_BO1 + n], b1 = mf[MF_BO1 + n + 1];
                float w0 = mf[MF_WO2 + n], w1 = mf[MF_WO2 + n + 1];
                pg  += frelu(d[mt][ng][0] + b0) * w0 + frelu(d[mt][ng][1] + b1) * w1;
                pg8 += frelu(d[mt][ng][2] + b0) * w0 + frelu(d[mt][ng][3] + b1) * w1;
            }
            pg  += __shfl_xor_sync(0xffffffffu, pg, 1);
            pg  += __shfl_xor_sync(0xffffffffu, pg, 2);
            pg8 += __shfl_xor_sync(0xffffffffu, pg8, 1);
            pg8 += __shfl_xor_sync(0xffffffffu, pg8, 2);
            if (i == 0) {
                mf[MF_SPPO + wn * 128 + r0] = pg;
                mf[MF_SPPO + wn * 128 + r0 + 8] = pg8;
            }
        }
        __syncthreads();                    // L3 reads of A complete

        // ---- rewrite A in place: A <- split(e + ray_enc) ----
        {
            const int m = tid >> 1, q = tid & 1;
#pragma unroll
            for (int jj = 0; jj < 16; jj++) {
                const int n = 32 * q + 2 * jj;
                unsigned off = (unsigned)(m * KPAD + n) * 2u;
                unsigned h = *(unsigned*)(smem + OB_AH + off);
                unsigned l = *(unsigned*)(smem + OB_AL + off);
                float e0 = __uint_as_float(h << 16) + __uint_as_float(l << 16);
                float e1 = __uint_as_float(h & 0xFFFF0000u) +
                           __uint_as_float(l & 0xFFFF0000u);
                e0 += mf[MF_RAY + n];
                e1 += mf[MF_RAY + n + 1];
                unsigned h2, l2;
                bsplit2(e0, e1, h2, l2);
                *(unsigned*)(smem + OB_AH + off) = h2;
                *(unsigned*)(smem + OB_AL + off) = l2;
            }
        }
        __syncthreads();

        // ---- L4: color head (reads A = e + ray_enc) ----
        mma_layer<4>(aHB, aLB, smW + 27648, smW + 32256, m0base, n0, lane, d);
        __syncthreads();                    // A dead; SPPC may alias it now
#pragma unroll
        for (int mt = 0; mt < 4; mt++) {
            int r0 = m0base + mt * 16 + g;
            float pgc[3] = {0.f, 0.f, 0.f};
            float pgc8[3] = {0.f, 0.f, 0.f};
#pragma unroll
            for (int ng = 0; ng < 2; ng++) {
                const int n = n0 + 8 * ng + 2 * i;
                float b0 = mf[MF_BC1 + n], b1 = mf[MF_BC1 + n + 1];
                float h00 = frelu(d[mt][ng][0] + b0), h01 = frelu(d[mt][ng][1] + b1);
                float h10 = frelu(d[mt][ng][2] + b0), h11 = frelu(d[mt][ng][3] + b1);
#pragma unroll
                for (int c = 0; c < 3; c++) {
                    float wc0 = mf[MF_WC2 + n * 3 + c];
                    float wc1 = mf[MF_WC2 + (n + 1) * 3 + c];
                    pgc[c]  += h00 * wc0 + h01 * wc1;
                    pgc8[c] += h10 * wc0 + h11 * wc1;
                }
            }
#pragma unroll
            for (int c = 0; c < 3; c++) {
                pgc[c]  += __shfl_xor_sync(0xffffffffu, pgc[c], 1);
                pgc[c]  += __shfl_xor_sync(0xffffffffu, pgc[c], 2);
                pgc8[c] += __shfl_xor_sync(0xffffffffu, pgc8[c], 1);
                pgc8[c] += __shfl_xor_sync(0xffffffffu, pgc8[c], 2);
                if (i == 0) {
                    sppc[c * 512 + wn * 128 + r0] = pgc[c];
                    sppc[c * 512 + wn * 128 + r0 + 8] = pgc8[c];
                }
            }
        }
        __syncthreads();

        // ---- per-sample finalize (threads 0..127) ----
        float am = 0.f, c0 = 0.f, c1 = 0.f, c2 = 0.f;
        if (tid < NS) {
            float raw = mf[MF_MISC];
            float a0 = mf[MF_MISC + 1], a1 = mf[MF_MISC + 2], a2 = mf[MF_MISC + 3];
#pragma unroll
            for (int w = 0; w < 4; w++) {
                raw += mf[MF_SPPO + w * 128 + tid];
                a0  += sppc[0 * 512 + w * 128 + tid];
                a1  += sppc[1 * 512 + w * 128 + tid];
                a2  += sppc[2 * 512 + w * 128 + tid];
            }
            float density = (raw > 0.f) ? (raw + log1pf(expf(-raw)))
                                        : log1pf(expf(raw));
            float delta = (fa - nr) / (float)NS;
            am = expf(-delta * density);
            c0 = 1.f / (1.f + expf(-a0));
            c1 = 1.f / (1.f + expf(-a1));
            c2 = 1.f / (1.f + expf(-a2));
        }

        // ---- transmittance scan + composite ----
        float excl = 1.f;
        if (tid < NS) {
            float incl = am;
#pragma unroll
            for (int off = 1; off < 32; off <<= 1) {
                float nn = __shfl_up_sync(0xffffffffu, incl, off);
                if (lane >= off) incl *= nn;
            }
            excl = __shfl_up_sync(0xffffffffu, incl, 1);
            if (lane == 0) excl = 1.f;
            if (lane == 31) mf[MF_WTOT + warp] = incl;
        }
        __syncthreads();
        if (tid < NS) {
            float w0 = mf[MF_WTOT + 0], w1 = mf[MF_WTOT + 1];
            float w2t = mf[MF_WTOT + 2], w3 = mf[MF_WTOT + 3];
            float pre = 1.f;
            if (warp > 0) pre *= w0;
            if (warp > 1) pre *= w1;
            if (warp > 2) pre *= w2t;
            float T = pre * excl;
            float total = w0 * w1 * w2t * w3;
            float wgt = T * (1.f - am);
            float r0 = wgt * c0, r1 = wgt * c1, r2 = wgt * c2;
#pragma unroll
            for (int off = 16; off > 0; off >>= 1) {
                r0 += __shfl_down_sync(0xffffffffu, r0, off);
                r1 += __shfl_down_sync(0xffffffffu, r1, off);
                r2 += __shfl_down_sync(0xffffffffu, r2, off);
            }
            if (lane == 0) {
                mf[MF_PART + warp * 3 + 0] = r0;
                mf[MF_PART + warp * 3 + 1] = r1;
                mf[MF_PART + warp * 3 + 2] = r2;
            }
            if (tid == 127) mf[MF_WTOT + 0] = total;
        }
        __syncthreads();
        if (tid == 0) {
            float s0 = 0.f, s1 = 0.f, s2 = 0.f;
#pragma unroll
            for (int w = 0; w < 4; w++) {
                s0 += mf[MF_PART + w * 3 + 0];
                s1 += mf[MF_PART + w * 3 + 1];
                s2 += mf[MF_PART + w * 3 + 2];
            }
            out[ray * 3 + 0] = s0;
            out[ray * 3 + 1] = s1;
            out[ray * 3 + 2] = s2;
            out[NRAYS * 3 + ray] = 1.f - mf[MF_WTOT + 0];
        }
        __syncthreads();
    }
}

extern "C" void kernel_launch(void* const* d_in, const int* in_sizes, int n_in,
                              void* d_out, int out_size) {
    const float* origins    = (const float*)d_in[0];
    const float* directions = (const float*)d_in[1];
    const float* nearv      = (const float*)d_in[2];
    const float* farv       = (const float*)d_in[3];
    const float* grid       = (const float*)d_in[4];
    const float* Wr  = (const float*)d_in[5];
    const float* br  = (const float*)d_in[6];
    const float* Wt1 = (const float*)d_in[7];
    const float* bt1 = (const float*)d_in[8];
    const float* Wt2 = (const float*)d_in[9];
    const float* bt2 = (const float*)d_in[10];
    const float* Wo1 = (const float*)d_in[11];
    const float* bo1 = (const float*)d_in[12];
    const float* Wo2 = (const float*)d_in[13];
    const float* bo2 = (const float*)d_in[14];
    const float* Wc1 = (const float*)d_in[15];
    const float* bc1 = (const float*)d_in[16];
    const float* Wc2 = (const float*)d_in[17];
    const float* bc2 = (const float*)d_in[18];
    float* out = (float*)d_out;

    cudaFuncSetAttribute(lightplane_kernel,
                         cudaFuncAttributeMaxDynamicSharedMemorySize, SMEM_BYTES);
    lightplane_kernel<<<NRAYS / RPB, NT, SMEM_BYTES>>>(
        origins, directions, nearv, farv, grid,
        Wr, br, Wt1, bt1, Wt2, bt2, Wo1, bo1, Wo2, bo2,
        Wc1, bc1, Wc2, bc2, out);
}

// round 16
// speedup vs baseline: 4.3244x; 1.0320x over previous
#include <cuda_runtime.h>
#include <cuda_bf16.h>
#include <math.h>

#define NRAYS 8192
#define NS    128
#define NT    256
#define NC    32
#define NH    64
#define NG    128
#define RPB   8
#define KPAD  72   // bf16 elems per A/W row (144B)

// smem byte offsets
#define OB_AH   0
#define OB_AL   18432
#define OB_W    36864          // 4 layers x 18432 B (hi 9216 + lo 9216) -> ends 110592
#define OB_MF   110592
// float offsets inside MF
#define MF_WO2   0
#define MF_WC2   64
#define MF_BT1   256
#define MF_BT2   320
#define MF_BO1   384
#define MF_BC1   448
#define MF_BR    512
#define MF_RAY   576
#define MF_HE    640
#define MF_WTOT  664
#define MF_PART  668
#define MF_MISC  680
#define MF_SPPO  684           // 2*128 = 256
#define MF_COUNT 940
#define SMEM_BYTES (OB_MF + MF_COUNT * 4)
// SPPC (3*256 floats = 3072 B) aliases the A buffer (dead after L4 mma)

typedef unsigned long long u64;

__device__ __forceinline__ float frelu(float x) { return x > 0.f ? x : 0.f; }

__device__ __forceinline__ u64 pack2(float a) {
    u64 r;
    unsigned u = __float_as_uint(a);
    asm("mov.b64 %0, {%1, %1};" : "=l"(r) : "r"(u));
    return r;
}
__device__ __forceinline__ void fma2(u64& d, u64 a, u64 b) {
    asm("fma.rn.f32x2 %0, %1, %2, %0;" : "+l"(d) : "l"(a), "l"(b));
}
__device__ __forceinline__ void unpack2(u64 v, float& lo, float& hi) {
    unsigned l, h;
    asm("mov.b64 {%0, %1}, %2;" : "=r"(l), "=r"(h) : "l"(v));
    lo = __uint_as_float(l);
    hi = __uint_as_float(h);
}
__device__ __forceinline__ unsigned smem_u32(const void* p) {
    unsigned a;
    asm("{ .reg .u64 t; cvta.to.shared.u64 t, %1; cvt.u32.u64 %0, t; }"
        : "=r"(a) : "l"(p));
    return a;
}
// split pair (x0 even-k, x1 odd-k) into packed bf16 hi/lo words (low half = x0)
__device__ __forceinline__ void bsplit2(float x0, float x1, unsigned& h, unsigned& l) {
    asm("cvt.rn.bf16x2.f32 %0, %1, %2;" : "=r"(h) : "f"(x1), "f"(x0));
    float h0 = __uint_as_float(h << 16);
    float h1 = __uint_as_float(h & 0xFFFF0000u);
    asm("cvt.rn.bf16x2.f32 %0, %1, %2;" : "=r"(l) : "f"(x1 - h1), "f"(x0 - h0));
}
__device__ __forceinline__ void ldm4(unsigned& a0, unsigned& a1, unsigned& a2,
                                     unsigned& a3, unsigned addr) {
    asm volatile("ldmatrix.sync.aligned.m8n8.x4.shared.b16 {%0,%1,%2,%3}, [%4];"
                 : "=r"(a0), "=r"(a1), "=r"(a2), "=r"(a3) : "r"(addr));
}
__device__ __forceinline__ void mmab(float* d, unsigned a0, unsigned a1,
                                     unsigned a2, unsigned a3,
                                     unsigned b0, unsigned b1) {
    asm volatile("mma.sync.aligned.m16n8k16.row.col.f32.bf16.bf16.f32 "
                 "{%0,%1,%2,%3},{%4,%5,%6,%7},{%8,%9},{%0,%1,%2,%3};"
                 : "+f"(d[0]), "+f"(d[1]), "+f"(d[2]), "+f"(d[3])
                 : "r"(a0), "r"(a1), "r"(a2), "r"(a3), "r"(b0), "r"(b1));
}

// Layer GEMM, warp covers rows [m0base, m0base+32), cols [n0, n0+32).
// A tiles loaded once, reused across all 4 n-groups.
template <int KS>
__device__ __forceinline__ void mma_layer(
    unsigned aH, unsigned aL,
    const unsigned short* wH, const unsigned short* wL,
    int m0base, int n0, int lane, float d[2][4][4]) {
    const int g = lane >> 2, i = lane & 3;
    const int lr = lane & 15, kc = (lane >> 4) << 3;
#pragma unroll
    for (int mt = 0; mt < 2; mt++)
#pragma unroll
        for (int ng = 0; ng < 4; ng++)
#pragma unroll
            for (int r = 0; r < 4; r++) d[mt][ng][r] = 0.f;
#pragma unroll
    for (int ks = 0; ks < KS; ks++) {
        const int k0 = ks * 16;
        unsigned bh[4][2], bl[4][2];
#pragma unroll
        for (int ng = 0; ng < 4; ng++) {
            const int wb = (n0 + 8 * ng + g) * KPAD + k0 + 2 * i;
            bh[ng][0] = *(const unsigned*)(wH + wb);
            bh[ng][1] = *(const unsigned*)(wH + wb + 8);
            bl[ng][0] = *(const unsigned*)(wL + wb);
            bl[ng][1] = *(const unsigned*)(wL + wb + 8);
        }
#pragma unroll
        for (int mt = 0; mt < 2; mt++) {
            unsigned off = (unsigned)((m0base + mt * 16 + lr) * KPAD + k0 + kc) * 2u;
            unsigned ah0, ah1, ah2, ah3, al0, al1, al2, al3;
            ldm4(ah0, ah1, ah2, ah3, aH + off);
            ldm4(al0, al1, al2, al3, aL + off);
#pragma unroll
            for (int ng = 0; ng < 4; ng++) {
                mmab(d[mt][ng], ah0, ah1, ah2, ah3, bh[ng][0], bh[ng][1]);
                mmab(d[mt][ng], ah0, ah1, ah2, ah3, bl[ng][0], bl[ng][1]);
                mmab(d[mt][ng], al0, al1, al2, al3, bh[ng][0], bh[ng][1]);
            }
        }
    }
}

__global__ void __launch_bounds__(NT, 2)
lightplane_kernel(const float* __restrict__ origins,
                  const float* __restrict__ directions,
                  const float* __restrict__ nearv,
                  const float* __restrict__ farv,
                  const float* __restrict__ grid,
                  const float* __restrict__ Wr,  const float* __restrict__ br,
                  const float* __restrict__ Wt1, const float* __restrict__ bt1,
                  const float* __restrict__ Wt2, const float* __restrict__ bt2,
                  const float* __restrict__ Wo1, const float* __restrict__ bo1,
                  const float* __restrict__ Wo2, const float* __restrict__ bo2,
                  const float* __restrict__ Wc1, const float* __restrict__ bc1,
                  const float* __restrict__ Wc2, const float* __restrict__ bc2,
                  float* __restrict__ out) {
    extern __shared__ char smem[];
    float* mf = (float*)(smem + OB_MF);
    float* sppc = (float*)smem;            // aliases A buffer (safe post-L4)
    unsigned short* smW = (unsigned short*)(smem + OB_W);
    const int tid = threadIdx.x;
    const int lane = tid & 31, warp = tid >> 5;
    const int wm = warp >> 1, wn = warp & 1;
    const int n0 = wn * 32;
    const int m0base = wm * 32;
    const int g = lane >> 2, i = lane & 3;
    const unsigned aHB = smem_u32(smem) + OB_AH;
    const unsigned aLB = smem_u32(smem) + OB_AL;

    // ---- stage weights: transpose to [n][KPAD], bf16 hi/lo ----
    {
        const float* Ws[4] = {Wt1, Wt2, Wo1, Wc1};
        const int Ks[4] = {NC, NH, NH, NH};
#pragma unroll 1
        for (int L = 0; L < 4; L++) {
            unsigned short* wh = smW + L * 9216;
            unsigned short* wl = wh + 4608;
            const float* W = Ws[L];
            const int tot = Ks[L] * 64;
            for (int idx = tid; idx < tot; idx += NT) {
                int k = idx >> 6, n = idx & 63;
                float w = W[idx];
                __nv_bfloat16 hb = __float2bfloat16(w);
                float hf = __bfloat162float(hb);
                __nv_bfloat16 lb = __float2bfloat16(w - hf);
                wh[n * KPAD + k] = *(unsigned short*)&hb;
                wl[n * KPAD + k] = *(unsigned short*)&lb;
            }
        }
        for (int x = tid; x < 192; x += NT) mf[MF_WC2 + x] = Wc2[x];
        if (tid < 64) {
            mf[MF_WO2 + tid] = Wo2[tid];
            mf[MF_BT1 + tid] = bt1[tid];
            mf[MF_BT2 + tid] = bt2[tid];
            mf[MF_BO1 + tid] = bo1[tid];
            mf[MF_BC1 + tid] = bc1[tid];
            mf[MF_BR + tid]  = br[tid];
        }
        if (tid == 64) mf[MF_MISC] = bo2[0];
        if (tid >= 65 && tid < 68) mf[MF_MISC + 1 + tid - 65] = bc2[tid - 65];
    }
    __syncthreads();

#pragma unroll 1
    for (int rr = 0; rr < RPB; rr++) {
        const int ray = blockIdx.x * RPB + rr;
        const float dx = directions[ray * 3 + 0];
        const float dy = directions[ray * 3 + 1];
        const float dz = directions[ray * 3 + 2];
        const float nr = nearv[ray];
        const float fa = farv[ray];
        const float ox = origins[ray * 3 + 0];
        const float oy = origins[ray * 3 + 1];
        const float oz = origins[ray * 3 + 2];

        if (tid < 9) {
            int f = tid / 3, d = tid % 3;
            float dv = (d == 0) ? dx : ((d == 1) ? dy : dz);
            float ang = dv * (float)(1 << f);
            mf[MF_HE + tid]     = sinf(ang);
            mf[MF_HE + 9 + tid] = cosf(ang);
        }
        if (tid >= 9 && tid < 12) {
            int d = tid - 9;
            mf[MF_HE + 18 + d] = (d == 0) ? dx : ((d == 1) ? dy : dz);
        }
        __syncthreads();                    // HE ready
        if (tid < NH) {
            float a = mf[MF_BR + tid];
#pragma unroll
            for (int k = 0; k < 21; k++)
                a = fmaf(mf[MF_HE + k], __ldg(&Wr[k * NH + tid]), a);
            mf[MF_RAY + tid] = a;
        }

        // ---- gather: 2 threads per sample, 16 channels each ----
        {
            const int m = tid >> 1, q = tid & 1;
            const float t = nr + (fa - nr) * (((float)m + 0.5f) / (float)NS);
            const float px = ox + t * dx;
            const float py = oy + t * dy;
            const float pz = oz + t * dz;
            u64 fac[8];
#pragma unroll
            for (int r = 0; r < 8; r++) fac[r] = 0ull;
            const float scale = 0.5f * (float)(NG - 1);
            float cx = (px + 1.f) * scale;
            float cy = (py + 1.f) * scale;
            float cz = (pz + 1.f) * scale;
            int x0 = min(max((int)floorf(cx), 0), NG - 1);
            int y0 = min(max((int)floorf(cy), 0), NG - 1);
            int z0 = min(max((int)floorf(cz), 0), NG - 1);
            int x1 = min(x0 + 1, NG - 1);
            int y1 = min(y0 + 1, NG - 1);
            int z1 = min(z0 + 1, NG - 1);
            float fx = cx - floorf(cx), fy = cy - floorf(cy), fz = cz - floorf(cz);
            float wx[2] = {1.f - fx, fx};
            float wy[2] = {1.f - fy, fy};
            float wz[2] = {1.f - fz, fz};
            int xs[2] = {x0, x1}, ys[2] = {y0, y1}, zs[2] = {z0, z1};
#pragma unroll
            for (int a = 0; a < 2; a++)
#pragma unroll
                for (int b = 0; b < 2; b++)
#pragma unroll
                    for (int c = 0; c < 2; c++) {
                        u64 wp = pack2(wx[a] * wy[b] * wz[c]);
                        const ulonglong2* g2 = (const ulonglong2*)(grid +
                            ((size_t)((zs[c] * NG + ys[b]) * NG + xs[a])) * NC + 16 * q);
#pragma unroll
                        for (int q4 = 0; q4 < 4; q4++) {
                            ulonglong2 v = __ldg(&g2[q4]);
                            fma2(fac[2 * q4], wp, v.x);
                            fma2(fac[2 * q4 + 1], wp, v.y);
                        }
                    }
#pragma unroll
            for (int r = 0; r < 8; r++) {
                float f0, f1;
                unpack2(fac[r], f0, f1);
                unsigned h, l;
                bsplit2(f0, f1, h, l);
                unsigned off = (unsigned)(m * KPAD + 16 * q + 2 * r) * 2u;
                *(unsigned*)(smem + OB_AH + off) = h;
                *(unsigned*)(smem + OB_AL + off) = l;
            }
        }
        __syncthreads();                    // A(feats), RAY ready

        float d[2][4][4];

        // ---- L1: K=32 ----
        mma_layer<2>(aHB, aLB, smW, smW + 4608, m0base, n0, lane, d);
        __syncthreads();                    // reads of A done
#pragma unroll
        for (int mt = 0; mt < 2; mt++)
#pragma unroll
            for (int ng = 0; ng < 4; ng++) {
                const int n = n0 + 8 * ng + 2 * i;
                float b0 = mf[MF_BT1 + n], b1 = mf[MF_BT1 + n + 1];
                int r0 = m0base + mt * 16 + g;
                unsigned h, l;
                bsplit2(frelu(d[mt][ng][0] + b0), frelu(d[mt][ng][1] + b1), h, l);
                unsigned off = (unsigned)(r0 * KPAD + n) * 2u;
                *(unsigned*)(smem + OB_AH + off) = h;
                *(unsigned*)(smem + OB_AL + off) = l;
                bsplit2(frelu(d[mt][ng][2] + b0), frelu(d[mt][ng][3] + b1), h, l);
                off = (unsigned)((r0 + 8) * KPAD + n) * 2u;
                *(unsigned*)(smem + OB_AH + off) = h;
                *(unsigned*)(smem + OB_AL + off) = l;
            }
        __syncthreads();

        // ---- L2: K=64 -> e ----
        mma_layer<4>(aHB, aLB, smW + 9216, smW + 13824, m0base, n0, lane, d);
        __syncthreads();
#pragma unroll
        for (int mt = 0; mt < 2; mt++)
#pragma unroll
            for (int ng = 0; ng < 4; ng++) {
                const int n = n0 + 8 * ng + 2 * i;
                float b0 = mf[MF_BT2 + n], b1 = mf[MF_BT2 + n + 1];
                int r0 = m0base + mt * 16 + g;
                unsigned h, l;
                bsplit2(frelu(d[mt][ng][0] + b0), frelu(d[mt][ng][1] + b1), h, l);
                unsigned off = (unsigned)(r0 * KPAD + n) * 2u;
                *(unsigned*)(smem + OB_AH + off) = h;
                *(unsigned*)(smem + OB_AL + off) = l;
                bsplit2(frelu(d[mt][ng][2] + b0), frelu(d[mt][ng][3] + b1), h, l);
                off = (unsigned)((r0 + 8) * KPAD + n) * 2u;
                *(unsigned*)(smem + OB_AH + off) = h;
                *(unsigned*)(smem + OB_AL + off) = l;
            }
        __syncthreads();

        // ---- L3: opacity head (reads A=e) ----
        mma_layer<4>(aHB, aLB, smW + 18432, smW + 23040, m0base, n0, lane, d);
#pragma unroll
        for (int mt = 0; mt < 2; mt++) {
            int r0 = m0base + mt * 16 + g;
            float pg = 0.f, pg8 = 0.f;
#pragma unroll
            for (int ng = 0; ng < 4; ng++) {
                const int n = n0 + 8 * ng + 2 * i;
                float b0 = mf[MF_BO1 + n], b1 = mf[MF_BO1 + n + 1];
                float w0 = mf[MF_WO2 + n], w1 = mf[MF_WO2 + n + 1];
                pg  += frelu(d[mt][ng][0] + b0) * w0 + frelu(d[mt][ng][1] + b1) * w1;
                pg8 += frelu(d[mt][ng][2] + b0) * w0 + frelu(d[mt][ng][3] + b1) * w1;
            }
            pg  += __shfl_xor_sync(0xffffffffu, pg, 1);
            pg  += __shfl_xor_sync(0xffffffffu, pg, 2);
            pg8 += __shfl_xor_sync(0xffffffffu, pg8, 1);
            pg8 += __shfl_xor_sync(0xffffffffu, pg8, 2);
            if (i == 0) {
                mf[MF_SPPO + wn * 128 + r0] = pg;
                mf[MF_SPPO + wn * 128 + r0 + 8] = pg8;
            }
        }
        __syncthreads();                    // L3 reads of A complete

        // ---- rewrite A in place: A <- split(e + ray_enc) ----
        {
            const int m = tid >> 1, q = tid & 1;
#pragma unroll
            for (int jj = 0; jj < 16; jj++) {
                const int n = 32 * q + 2 * jj;
                unsigned off = (unsigned)(m * KPAD + n) * 2u;
                unsigned h = *(unsigned*)(smem + OB_AH + off);
                unsigned l = *(unsigned*)(smem + OB_AL + off);
                float e0 = __uint_as_float(h << 16) + __uint_as_float(l << 16);
                float e1 = __uint_as_float(h & 0xFFFF0000u) +
                           __uint_as_float(l & 0xFFFF0000u);
                e0 += mf[MF_RAY + n];
                e1 += mf[MF_RAY + n + 1];
                unsigned h2, l2;
                bsplit2(e0, e1, h2, l2);
                *(unsigned*)(smem + OB_AH + off) = h2;
                *(unsigned*)(smem + OB_AL + off) = l2;
            }
        }
        __syncthreads();

        // ---- L4: color head (reads A = e + ray_enc) ----
        mma_layer<4>(aHB, aLB, smW + 27648, smW + 32256, m0base, n0, lane, d);
        __syncthreads();                    // A dead; SPPC may alias it now
#pragma unroll
        for (int mt = 0; mt < 2; mt++) {
            int r0 = m0base + mt * 16 + g;
            float pgc[3] = {0.f, 0.f, 0.f};
            float pgc8[3] = {0.f, 0.f, 0.f};
#pragma unroll
            for (int ng = 0; ng < 4; ng++) {
                const int n = n0 + 8 * ng + 2 * i;
                float b0 = mf[MF_BC1 + n], b1 = mf[MF_BC1 + n + 1];
                float h00 = frelu(d[mt][ng][0] + b0), h01 = frelu(d[mt][ng][1] + b1);
                float h10 = frelu(d[mt][ng][2] + b0), h11 = frelu(d[mt][ng][3] + b1);
#pragma unroll
                for (int c = 0; c < 3; c++) {
                    float wc0 = mf[MF_WC2 + n * 3 + c];
                    float wc1 = mf[MF_WC2 + (n + 1) * 3 + c];
                    pgc[c]  += h00 * wc0 + h01 * wc1;
                    pgc8[c] += h10 * wc0 + h11 * wc1;
                }
            }
#pragma unroll
            for (int c = 0; c < 3; c++) {
                pgc[c]  += __shfl_xor_sync(0xffffffffu, pgc[c], 1);
                pgc[c]  += __shfl_xor_sync(0xffffffffu, pgc[c], 2);
                pgc8[c] += __shfl_xor_sync(0xffffffffu, pgc8[c], 1);
                pgc8[c] += __shfl_xor_sync(0xffffffffu, pgc8[c], 2);
                if (i == 0) {
                    sppc[c * 256 + wn * 128 + r0] = pgc[c];
                    sppc[c * 256 + wn * 128 + r0 + 8] = pgc8[c];
                }
            }
        }
        __syncthreads();

        // ---- per-sample finalize (threads 0..127) ----
        float am = 0.f, c0 = 0.f, c1 = 0.f, c2 = 0.f;
        if (tid < NS) {
            float raw = mf[MF_MISC];
            float a0 = mf[MF_MISC + 1], a1 = mf[MF_MISC + 2], a2 = mf[MF_MISC + 3];
#pragma unroll
            for (int w = 0; w < 2; w++) {
                raw += mf[MF_SPPO + w * 128 + tid];
                a0  += sppc[0 * 256 + w * 128 + tid];
                a1  += sppc[1 * 256 + w * 128 + tid];
                a2  += sppc[2 * 256 + w * 128 + tid];
            }
            float density = (raw > 0.f) ? (raw + log1pf(expf(-raw)))
                                        : log1pf(expf(raw));
            float delta = (fa - nr) / (float)NS;
            am = expf(-delta * density);
            c0 = 1.f / (1.f + expf(-a0));
            c1 = 1.f / (1.f + expf(-a1));
            c2 = 1.f / (1.f + expf(-a2));
        }

        // ---- transmittance scan + composite ----
        float excl = 1.f;
        if (tid < NS) {
            float incl = am;
#pragma unroll
            for (int off = 1; off < 32; off <<= 1) {
                float nn = __shfl_up_sync(0xffffffffu, incl, off);
                if (lane >= off) incl *= nn;
            }
            excl = __shfl_up_sync(0xffffffffu, incl, 1);
            if (lane == 0) excl = 1.f;
            if (lane == 31) mf[MF_WTOT + warp] = incl;
        }
        __syncthreads();
        if (tid < NS) {
            float w0 = mf[MF_WTOT + 0], w1 = mf[MF_WTOT + 1];
            float w2t = mf[MF_WTOT + 2], w3 = mf[MF_WTOT + 3];
            float pre = 1.f;
            if (warp > 0) pre *= w0;
            if (warp > 1) pre *= w1;
            if (warp > 2) pre *= w2t;
            float T = pre * excl;
            float total = w0 * w1 * w2t * w3;
            float wgt = T * (1.f - am);
            float r0 = wgt * c0, r1 = wgt * c1, r2 = wgt * c2;
#pragma unroll
            for (int off = 16; off > 0; off >>= 1) {
                r0 += __shfl_down_sync(0xffffffffu, r0, off);
                r1 += __shfl_down_sync(0xffffffffu, r1, off);
                r2 += __shfl_down_sync(0xffffffffu, r2, off);
            }
            if (lane == 0) {
                mf[MF_PART + warp * 3 + 0] = r0;
                mf[MF_PART + warp * 3 + 1] = r1;
                mf[MF_PART + warp * 3 + 2] = r2;
            }
            if (tid == 127) mf[MF_WTOT + 0] = total;
        }
        __syncthreads();
        if (tid == 0) {
            float s0 = 0.f, s1 = 0.f, s2 = 0.f;
#pragma unroll
            for (int w = 0; w < 4; w++) {
                s0 += mf[MF_PART + w * 3 + 0];
                s1 += mf[MF_PART + w * 3 + 1];
                s2 += mf[MF_PART + w * 3 + 2];
            }
            out[ray * 3 + 0] = s0;
            out[ray * 3 + 1] = s1;
            out[ray * 3 + 2] = s2;
            out[NRAYS * 3 + ray] = 1.f - mf[MF_WTOT + 0];
        }
        __syncthreads();
    }
}

extern "C" void kernel_launch(void* const* d_in, const int* in_sizes, int n_in,
                              void* d_out, int out_size) {
    const float* origins    = (const float*)d_in[0];
    const float* directions = (const float*)d_in[1];
    const float* nearv      = (const float*)d_in[2];
    const float* farv       = (const float*)d_in[3];
    const float* grid       = (const float*)d_in[4];
    const float* Wr  = (const float*)d_in[5];
    const float* br  = (const float*)d_in[6];
    const float* Wt1 = (const float*)d_in[7];
    const float* bt1 = (const float*)d_in[8];
    const float* Wt2 = (const float*)d_in[9];
    const float* bt2 = (const float*)d_in[10];
    const float* Wo1 = (const float*)d_in[11];
    const float* bo1 = (const float*)d_in[12];
    const float* Wo2 = (const float*)d_in[13];
    const float* bo2 = (const float*)d_in[14];
    const float* Wc1 = (const float*)d_in[15];
    const float* bc1 = (const float*)d_in[16];
    const float* Wc2 = (const float*)d_in[17];
    const float* bc2 = (const float*)d_in[18];
    float* out = (float*)d_out;

    cudaFuncSetAttribute(lightplane_kernel,
                         cudaFuncAttributeMaxDynamicSharedMemorySize, SMEM_BYTES);
    lightplane_kernel<<<NRAYS / RPB, NT, SMEM_BYTES>>>(
        origins, directions, nearv, farv, grid,
        Wr, br, Wt1, bt1, Wt2, bt2, Wo1, bo1, Wo2, bo2,
        Wc1, bc1, Wc2, bc2, out);
}

// round 17
// speedup vs baseline: 4.4416x; 1.0271x over previous
#include <cuda_runtime.h>
#include <cuda_bf16.h>
#include <math.h>

#define NRAYS 8192
#define NS    128
#define NT    256
#define NC    32
#define NH    64
#define NG    128
#define RPB   8
#define KPAD  72   // bf16 elems per A/W row (144B)

// smem byte offsets
#define OB_AH   0
#define OB_AL   18432
#define OB_W    36864          // 4 layers x 18432 B -> ends 110592
#define OB_MF   110592
// float offsets inside MF
#define MF_WO2   0
#define MF_WC2   64
#define MF_BT1   256
#define MF_BT2   320
#define MF_BO1   384
#define MF_BC1   448
#define MF_BR    512
#define MF_RAY   576          // 4 groups x 64
#define MF_HE    832          // 4 groups x 24
#define MF_MISC  928          // bo2(1)+bc2(3)
#define MF_SPPO  932          // 2*128
#define MF_COUNT 1188
#define SMEM_BYTES (OB_MF + MF_COUNT * 4)
// Per-group scratch (post-L4 only) aliases the group's own A rows:
//   gs = smem + OB_AH + wm*4608 ; floats:
//   [wn*96 + c*32 + rloc] color partials, [192+rloc] am, [224+c*32+rloc] colors

typedef unsigned long long u64;

__device__ __forceinline__ float frelu(float x) { return x > 0.f ? x : 0.f; }

__device__ __forceinline__ u64 pack2(float a) {
    u64 r;
    unsigned u = __float_as_uint(a);
    asm("mov.b64 %0, {%1, %1};" : "=l"(r) : "r"(u));
    return r;
}
__device__ __forceinline__ void fma2(u64& d, u64 a, u64 b) {
    asm("fma.rn.f32x2 %0, %1, %2, %0;" : "+l"(d) : "l"(a), "l"(b));
}
__device__ __forceinline__ void unpack2(u64 v, float& lo, float& hi) {
    unsigned l, h;
    asm("mov.b64 {%0, %1}, %2;" : "=r"(l), "=r"(h) : "l"(v));
    lo = __uint_as_float(l);
    hi = __uint_as_float(h);
}
__device__ __forceinline__ unsigned smem_u32(const void* p) {
    unsigned a;
    asm("{ .reg .u64 t; cvta.to.shared.u64 t, %1; cvt.u32.u64 %0, t; }"
        : "=r"(a) : "l"(p));
    return a;
}
__device__ __forceinline__ void bsplit2(float x0, float x1, unsigned& h, unsigned& l) {
    asm("cvt.rn.bf16x2.f32 %0, %1, %2;" : "=r"(h) : "f"(x1), "f"(x0));
    float h0 = __uint_as_float(h << 16);
    float h1 = __uint_as_float(h & 0xFFFF0000u);
    asm("cvt.rn.bf16x2.f32 %0, %1, %2;" : "=r"(l) : "f"(x1 - h1), "f"(x0 - h0));
}
__device__ __forceinline__ void ldm4(unsigned& a0, unsigned& a1, unsigned& a2,
                                     unsigned& a3, unsigned addr) {
    asm volatile("ldmatrix.sync.aligned.m8n8.x4.shared.b16 {%0,%1,%2,%3}, [%4];"
                 : "=r"(a0), "=r"(a1), "=r"(a2), "=r"(a3) : "r"(addr));
}
__device__ __forceinline__ void mmab(float* d, unsigned a0, unsigned a1,
                                     unsigned a2, unsigned a3,
                                     unsigned b0, unsigned b1) {
    asm volatile("mma.sync.aligned.m16n8k16.row.col.f32.bf16.bf16.f32 "
                 "{%0,%1,%2,%3},{%4,%5,%6,%7},{%8,%9},{%0,%1,%2,%3};"
                 : "+f"(d[0]), "+f"(d[1]), "+f"(d[2]), "+f"(d[3])
                 : "r"(a0), "r"(a1), "r"(a2), "r"(a3), "r"(b0), "r"(b1));
}
#define NBAR(id) asm volatile("bar.sync %0, %1;" :: "r"(id), "r"(64) : "memory")

// Layer GEMM, warp covers rows [m0base, m0base+32), cols [n0, n0+32).
template <int KS>
__device__ __forceinline__ void mma_layer(
    unsigned aH, unsigned aL,
    const unsigned short* wH, const unsigned short* wL,
    int m0base, int n0, int lane, float d[2][4][4]) {
    const int g = lane >> 2, i = lane & 3;
    const int lr = lane & 15, kc = (lane >> 4) << 3;
#pragma unroll
    for (int mt = 0; mt < 2; mt++)
#pragma unroll
        for (int ng = 0; ng < 4; ng++)
#pragma unroll
            for (int r = 0; r < 4; r++) d[mt][ng][r] = 0.f;
#pragma unroll
    for (int ks = 0; ks < KS; ks++) {
        const int k0 = ks * 16;
        unsigned bh[4][2], bl[4][2];
#pragma unroll
        for (int ng = 0; ng < 4; ng++) {
            const int wb = (n0 + 8 * ng + g) * KPAD + k0 + 2 * i;
            bh[ng][0] = *(const unsigned*)(wH + wb);
            bh[ng][1] = *(const unsigned*)(wH + wb + 8);
            bl[ng][0] = *(const unsigned*)(wL + wb);
            bl[ng][1] = *(const unsigned*)(wL + wb + 8);
        }
#pragma unroll
        for (int mt = 0; mt < 2; mt++) {
            unsigned off = (unsigned)((m0base + mt * 16 + lr) * KPAD + k0 + kc) * 2u;
            unsigned ah0, ah1, ah2, ah3, al0, al1, al2, al3;
            ldm4(ah0, ah1, ah2, ah3, aH + off);
            ldm4(al0, al1, al2, al3, aL + off);
#pragma unroll
            for (int ng = 0; ng < 4; ng++) {
                mmab(d[mt][ng], ah0, ah1, ah2, ah3, bh[ng][0], bh[ng][1]);
                mmab(d[mt][ng], ah0, ah1, ah2, ah3, bl[ng][0], bl[ng][1]);
                mmab(d[mt][ng], al0, al1, al2, al3, bh[ng][0], bh[ng][1]);
            }
        }
    }
}

__global__ void __launch_bounds__(NT, 2)
lightplane_kernel(const float* __restrict__ origins,
                  const float* __restrict__ directions,
                  const float* __restrict__ nearv,
                  const float* __restrict__ farv,
                  const float* __restrict__ grid,
                  const float* __restrict__ Wr,  const float* __restrict__ br,
                  const float* __restrict__ Wt1, const float* __restrict__ bt1,
                  const float* __restrict__ Wt2, const float* __restrict__ bt2,
                  const float* __restrict__ Wo1, const float* __restrict__ bo1,
                  const float* __restrict__ Wo2, const float* __restrict__ bo2,
                  const float* __restrict__ Wc1, const float* __restrict__ bc1,
                  const float* __restrict__ Wc2, const float* __restrict__ bc2,
                  float* __restrict__ out) {
    extern __shared__ char smem[];
    float* mf = (float*)(smem + OB_MF);
    unsigned short* smW = (unsigned short*)(smem + OB_W);
    const int tid = threadIdx.x;
    const int lane = tid & 31, warp = tid >> 5;
    const int wm = warp >> 1, wn = warp & 1;
    const int gb = wm + 1;                 // named barrier id (1..4)
    const int tg = tid & 63;               // thread-in-group
    const int n0 = wn * 32;
    const int m0base = wm * 32;
    const int g = lane >> 2, i = lane & 3;
    const unsigned aHB = smem_u32(smem) + OB_AH;
    const unsigned aLB = smem_u32(smem) + OB_AL;
    float* gs = (float*)(smem + OB_AH + wm * 4608);   // group scratch (post-L4)

    // ---- stage weights: transpose to [n][KPAD], bf16 hi/lo ----
    {
        const float* Ws[4] = {Wt1, Wt2, Wo1, Wc1};
        const int Ks[4] = {NC, NH, NH, NH};
#pragma unroll 1
        for (int L = 0; L < 4; L++) {
            unsigned short* wh = smW + L * 9216;
            unsigned short* wl = wh + 4608;
            const float* W = Ws[L];
            const int tot = Ks[L] * 64;
            for (int idx = tid; idx < tot; idx += NT) {
                int k = idx >> 6, n = idx & 63;
                float w = W[idx];
                __nv_bfloat16 hb = __float2bfloat16(w);
                float hf = __bfloat162float(hb);
                __nv_bfloat16 lb = __float2bfloat16(w - hf);
                wh[n * KPAD + k] = *(unsigned short*)&hb;
                wl[n * KPAD + k] = *(unsigned short*)&lb;
            }
        }
        for (int x = tid; x < 192; x += NT) mf[MF_WC2 + x] = Wc2[x];
        if (tid < 64) {
            mf[MF_WO2 + tid] = Wo2[tid];
            mf[MF_BT1 + tid] = bt1[tid];
            mf[MF_BT2 + tid] = bt2[tid];
            mf[MF_BO1 + tid] = bo1[tid];
            mf[MF_BC1 + tid] = bc1[tid];
            mf[MF_BR + tid]  = br[tid];
        }
        if (tid == 64) mf[MF_MISC] = bo2[0];
        if (tid >= 65 && tid < 68) mf[MF_MISC + 1 + tid - 65] = bc2[tid - 65];
    }
    __syncthreads();

#pragma unroll 1
    for (int rr = 0; rr < RPB; rr++) {
        const int ray = blockIdx.x * RPB + rr;
        const float dx = directions[ray * 3 + 0];
        const float dy = directions[ray * 3 + 1];
        const float dz = directions[ray * 3 + 2];
        const float nr = nearv[ray];
        const float fa = farv[ray];
        const float ox = origins[ray * 3 + 0];
        const float oy = origins[ray * 3 + 1];
        const float oz = origins[ray * 3 + 2];

        // ---- per-group harmonic encoding ----
        if (tg < 9) {
            int f = tg / 3, d = tg % 3;
            float dv = (d == 0) ? dx : ((d == 1) ? dy : dz);
            float ang = dv * (float)(1 << f);
            mf[MF_HE + 24 * wm + tg]     = sinf(ang);
            mf[MF_HE + 24 * wm + 9 + tg] = cosf(ang);
        }
        if (tg >= 9 && tg < 12) {
            int d = tg - 9;
            mf[MF_HE + 24 * wm + 18 + d] = (d == 0) ? dx : ((d == 1) ? dy : dz);
        }
        NBAR(gb);                           // HE ready (group)

        // per-group ray encoding (each thread one column)
        {
            float a = mf[MF_BR + tg];
#pragma unroll
            for (int k = 0; k < 21; k++)
                a = fmaf(mf[MF_HE + 24 * wm + k], __ldg(&Wr[k * NH + tg]), a);
            mf[MF_RAY + 64 * wm + tg] = a;
        }

        // ---- gather: group's 32 samples, 2 threads/sample ----
        {
            const int m = 32 * wm + (tg >> 1), q = tg & 1;
            const float t = nr + (fa - nr) * (((float)m + 0.5f) / (float)NS);
            const float px = ox + t * dx;
            const float py = oy + t * dy;
            const float pz = oz + t * dz;
            u64 fac[8];
#pragma unroll
            for (int r = 0; r < 8; r++) fac[r] = 0ull;
            const float scale = 0.5f * (float)(NG - 1);
            float cx = (px + 1.f) * scale;
            float cy = (py + 1.f) * scale;
            float cz = (pz + 1.f) * scale;
            int x0 = min(max((int)floorf(cx), 0), NG - 1);
            int y0 = min(max((int)floorf(cy), 0), NG - 1);
            int z0 = min(max((int)floorf(cz), 0), NG - 1);
            int x1 = min(x0 + 1, NG - 1);
            int y1 = min(y0 + 1, NG - 1);
            int z1 = min(z0 + 1, NG - 1);
            float fx = cx - floorf(cx), fy = cy - floorf(cy), fz = cz - floorf(cz);
            float wx[2] = {1.f - fx, fx};
            float wy[2] = {1.f - fy, fy};
            float wz[2] = {1.f - fz, fz};
            int xs[2] = {x0, x1}, ys[2] = {y0, y1}, zs[2] = {z0, z1};
#pragma unroll
            for (int a = 0; a < 2; a++)
#pragma unroll
                for (int b = 0; b < 2; b++)
#pragma unroll
                    for (int c = 0; c < 2; c++) {
                        u64 wp = pack2(wx[a] * wy[b] * wz[c]);
                        const ulonglong2* g2 = (const ulonglong2*)(grid +
                            ((size_t)((zs[c] * NG + ys[b]) * NG + xs[a])) * NC + 16 * q);
#pragma unroll
                        for (int q4 = 0; q4 < 4; q4++) {
                            ulonglong2 v = __ldg(&g2[q4]);
                            fma2(fac[2 * q4], wp, v.x);
                            fma2(fac[2 * q4 + 1], wp, v.y);
                        }
                    }
#pragma unroll
            for (int r = 0; r < 8; r++) {
                float f0, f1;
                unpack2(fac[r], f0, f1);
                unsigned h, l;
                bsplit2(f0, f1, h, l);
                unsigned off = (unsigned)(m * KPAD + 16 * q + 2 * r) * 2u;
                *(unsigned*)(smem + OB_AH + off) = h;
                *(unsigned*)(smem + OB_AL + off) = l;
            }
        }
        NBAR(gb);                           // A(feats), RAY ready (group)

        float d[2][4][4];

        // ---- L1: K=32 ----
        mma_layer<2>(aHB, aLB, smW, smW + 4608, m0base, n0, lane, d);
        NBAR(gb);
#pragma unroll
        for (int mt = 0; mt < 2; mt++)
#pragma unroll
            for (int ng = 0; ng < 4; ng++) {
                const int n = n0 + 8 * ng + 2 * i;
                float b0 = mf[MF_BT1 + n], b1 = mf[MF_BT1 + n + 1];
                int r0 = m0base + mt * 16 + g;
                unsigned h, l;
                bsplit2(frelu(d[mt][ng][0] + b0), frelu(d[mt][ng][1] + b1), h, l);
                unsigned off = (unsigned)(r0 * KPAD + n) * 2u;
                *(unsigned*)(smem + OB_AH + off) = h;
                *(unsigned*)(smem + OB_AL + off) = l;
                bsplit2(frelu(d[mt][ng][2] + b0), frelu(d[mt][ng][3] + b1), h, l);
                off = (unsigned)((r0 + 8) * KPAD + n) * 2u;
                *(unsigned*)(smem + OB_AH + off) = h;
                *(unsigned*)(smem + OB_AL + off) = l;
            }
        NBAR(gb);

        // ---- L2: K=64 -> e ----
        mma_layer<4>(aHB, aLB, smW + 9216, smW + 13824, m0base, n0, lane, d);
        NBAR(gb);
#pragma unroll
        for (int mt = 0; mt < 2; mt++)
#pragma unroll
            for (int ng = 0; ng < 4; ng++) {
                const int n = n0 + 8 * ng + 2 * i;
                float b0 = mf[MF_BT2 + n], b1 = mf[MF_BT2 + n + 1];
                int r0 = m0base + mt * 16 + g;
                unsigned h, l;
                bsplit2(frelu(d[mt][ng][0] + b0), frelu(d[mt][ng][1] + b1), h, l);
                unsigned off = (unsigned)(r0 * KPAD + n) * 2u;
                *(unsigned*)(smem + OB_AH + off) = h;
                *(unsigned*)(smem + OB_AL + off) = l;
                bsplit2(frelu(d[mt][ng][2] + b0), frelu(d[mt][ng][3] + b1), h, l);
                off = (unsigned)((r0 + 8) * KPAD + n) * 2u;
                *(unsigned*)(smem + OB_AH + off) = h;
                *(unsigned*)(smem + OB_AL + off) = l;
            }
        NBAR(gb);

        // ---- L3: opacity head (reads A=e) ----
        mma_layer<4>(aHB, aLB, smW + 18432, smW + 23040, m0base, n0, lane, d);
#pragma unroll
        for (int mt = 0; mt < 2; mt++) {
            int r0 = m0base + mt * 16 + g;
            float pg = 0.f, pg8 = 0.f;
#pragma unroll
            for (int ng = 0; ng < 4; ng++) {
                const int n = n0 + 8 * ng + 2 * i;
                float b0 = mf[MF_BO1 + n], b1 = mf[MF_BO1 + n + 1];
                float w0 = mf[MF_WO2 + n], w1 = mf[MF_WO2 + n + 1];
                pg  += frelu(d[mt][ng][0] + b0) * w0 + frelu(d[mt][ng][1] + b1) * w1;
                pg8 += frelu(d[mt][ng][2] + b0) * w0 + frelu(d[mt][ng][3] + b1) * w1;
            }
            pg  += __shfl_xor_sync(0xffffffffu, pg, 1);
            pg  += __shfl_xor_sync(0xffffffffu, pg, 2);
            pg8 += __shfl_xor_sync(0xffffffffu, pg8, 1);
            pg8 += __shfl_xor_sync(0xffffffffu, pg8, 2);
            if (i == 0) {
                mf[MF_SPPO + wn * 128 + r0] = pg;
                mf[MF_SPPO + wn * 128 + r0 + 8] = pg8;
            }
        }
        NBAR(gb);                           // L3 reads of A complete

        // ---- rewrite A in place: A <- split(e + ray_enc) (group rows) ----
        {
            const int m = 32 * wm + (tg >> 1), q = tg & 1;
#pragma unroll
            for (int jj = 0; jj < 16; jj++) {
                const int n = 32 * q + 2 * jj;
                unsigned off = (unsigned)(m * KPAD + n) * 2u;
                unsigned h = *(unsigned*)(smem + OB_AH + off);
                unsigned l = *(unsigned*)(smem + OB_AL + off);
                float e0 = __uint_as_float(h << 16) + __uint_as_float(l << 16);
                float e1 = __uint_as_float(h & 0xFFFF0000u) +
                           __uint_as_float(l & 0xFFFF0000u);
                e0 += mf[MF_RAY + 64 * wm + n];
                e1 += mf[MF_RAY + 64 * wm + n + 1];
                unsigned h2, l2;
                bsplit2(e0, e1, h2, l2);
                *(unsigned*)(smem + OB_AH + off) = h2;
                *(unsigned*)(smem + OB_AL + off) = l2;
            }
        }
        NBAR(gb);

        // ---- L4: color head (reads A = e + ray_enc) ----
        mma_layer<4>(aHB, aLB, smW + 27648, smW + 32256, m0base, n0, lane, d);
        NBAR(gb);                           // group's A reads done -> scratch OK
#pragma unroll
        for (int mt = 0; mt < 2; mt++) {
            int rl = mt * 16 + g;
            float pgc[3] = {0.f, 0.f, 0.f};
            float pgc8[3] = {0.f, 0.f, 0.f};
#pragma unroll
            for (int ng = 0; ng < 4; ng++) {
                const int n = n0 + 8 * ng + 2 * i;
                float b0 = mf[MF_BC1 + n], b1 = mf[MF_BC1 + n + 1];
                float h00 = frelu(d[mt][ng][0] + b0), h01 = frelu(d[mt][ng][1] + b1);
                float h10 = frelu(d[mt][ng][2] + b0), h11 = frelu(d[mt][ng][3] + b1);
#pragma unroll
                for (int c = 0; c < 3; c++) {
                    float wc0 = mf[MF_WC2 + n * 3 + c];
                    float wc1 = mf[MF_WC2 + (n + 1) * 3 + c];
                    pgc[c]  += h00 * wc0 + h01 * wc1;
                    pgc8[c] += h10 * wc0 + h11 * wc1;
                }
            }
#pragma unroll
            for (int c = 0; c < 3; c++) {
                pgc[c]  += __shfl_xor_sync(0xffffffffu, pgc[c], 1);
                pgc[c]  += __shfl_xor_sync(0xffffffffu, pgc[c], 2);
                pgc8[c] += __shfl_xor_sync(0xffffffffu, pgc8[c], 1);
                pgc8[c] += __shfl_xor_sync(0xffffffffu, pgc8[c], 2);
                if (i == 0) {
                    gs[wn * 96 + c * 32 + rl] = pgc[c];
                    gs[wn * 96 + c * 32 + rl + 8] = pgc8[c];
                }
            }
        }
        NBAR(gb);                           // color partials ready (group)

        // ---- group finalize: wn==0 warp, one lane per sample ----
        if (wn == 0) {
            int rl = lane;
            int s = 32 * wm + lane;
            float raw = mf[MF_MISC] + mf[MF_SPPO + s] + mf[MF_SPPO + 128 + s];
            float a0 = mf[MF_MISC + 1] + gs[0 + rl] + gs[96 + rl];
            float a1 = mf[MF_MISC + 2] + gs[32 + rl] + gs[96 + 32 + rl];
            float a2 = mf[MF_MISC + 3] + gs[64 + rl] + gs[96 + 64 + rl];
            float density = (raw > 0.f) ? (raw + log1pf(expf(-raw)))
                                        : log1pf(expf(raw));
            float delta = (fa - nr) / (float)NS;
            gs[192 + rl] = expf(-delta * density);   // am = 1 - alpha
            gs[224 + rl]      = 1.f / (1.f + expf(-a0));
            gs[224 + 32 + rl] = 1.f / (1.f + expf(-a1));
            gs[224 + 64 + rl] = 1.f / (1.f + expf(-a2));
        }
        __syncthreads();                    // all groups' am/colors ready

        // ---- warp 0: full scan + composite + output ----
        if (warp == 0) {
            float am[4], cc0[4], cc1[4], cc2[4];
#pragma unroll
            for (int j = 0; j < 4; j++) {
                int s = lane * 4 + j;
                const float* sb = (const float*)(smem + OB_AH + (s >> 5) * 4608);
                int rl = s & 31;
                am[j]  = sb[192 + rl];
                cc0[j] = sb[224 + rl];
                cc1[j] = sb[224 + 32 + rl];
                cc2[j] = sb[224 + 64 + rl];
            }
            float p0 = am[0];
            float p1 = p0 * am[1];
            float p2 = p1 * am[2];
            float p3 = p2 * am[3];
            float incl = p3;
#pragma unroll
            for (int off = 1; off < 32; off <<= 1) {
                float v = __shfl_up_sync(0xffffffffu, incl, off);
                if (lane >= off) incl *= v;
            }
            float excl = __shfl_up_sync(0xffffffffu, incl, 1);
            if (lane == 0) excl = 1.f;
            float T0 = excl, T1 = excl * p0, T2 = excl * p1, T3 = excl * p2;
            float w0 = T0 * (1.f - am[0]);
            float w1 = T1 * (1.f - am[1]);
            float w2 = T2 * (1.f - am[2]);
            float w3 = T3 * (1.f - am[3]);
            float r0 = w0 * cc0[0] + w1 * cc0[1] + w2 * cc0[2] + w3 * cc0[3];
            float r1 = w0 * cc1[0] + w1 * cc1[1] + w2 * cc1[2] + w3 * cc1[3];
            float r2 = w0 * cc2[0] + w1 * cc2[1] + w2 * cc2[2] + w3 * cc2[3];
            float total = __shfl_sync(0xffffffffu, incl, 31);
#pragma unroll
            for (int off = 16; off > 0; off >>= 1) {
                r0 += __shfl_down_sync(0xffffffffu, r0, off);
                r1 += __shfl_down_sync(0xffffffffu, r1, off);
                r2 += __shfl_down_sync(0xffffffffu, r2, off);
            }
            if (lane == 0) {
                out[ray * 3 + 0] = r0;
                out[ray * 3 + 1] = r1;
                out[ray * 3 + 2] = r2;
                out[NRAYS * 3 + ray] = 1.f - total;
            }
        }
        __syncthreads();                    // protect scratch before next gather
    }
}

extern "C" void kernel_launch(void* const* d_in, const int* in_sizes, int n_in,
                              void* d_out, int out_size) {
    const float* origins    = (const float*)d_in[0];
    const float* directions = (const float*)d_in[1];
    const float* nearv      = (const float*)d_in[2];
    const float* farv       = (const float*)d_in[3];
    const float* grid       = (const float*)d_in[4];
    const float* Wr  = (const float*)d_in[5];
    const float* br  = (const float*)d_in[6];
    const float* Wt1 = (const float*)d_in[7];
    const float* bt1 = (const float*)d_in[8];
    const float* Wt2 = (const float*)d_in[9];
    const float* bt2 = (const float*)d_in[10];
    const float* Wo1 = (const float*)d_in[11];
    const float* bo1 = (const float*)d_in[12];
    const float* Wo2 = (const float*)d_in[13];
    const float* bo2 = (const float*)d_in[14];
    const float* Wc1 = (const float*)d_in[15];
    const float* bc1 = (const float*)d_in[16];
    const float* Wc2 = (const float*)d_in[17];
    const float* bc2 = (const float*)d_in[18];
    float* out = (float*)d_out;

    cudaFuncSetAttribute(lightplane_kernel,
                         cudaFuncAttributeMaxDynamicSharedMemorySize, SMEM_BYTES);
    lightplane_kernel<<<NRAYS / RPB, NT, SMEM_BYTES>>>(
        origins, directions, nearv, farv, grid,
        Wr, br, Wt1, bt1, Wt2, bt2, Wo1, bo1, Wo2, bo2,
        Wc1, bc1, Wc2, bc2, out);
}